// round 12
// baseline (speedup 1.0000x reference)
#include <cuda_runtime.h>
#include <cuda_bf16.h>
#include <cstdint>

// ============================================================================
// ChebConvNet fused MLP via mma.sync (HMMA, baseline PTX).
//   h=silu(x@W0+b0); h=silu(h@W1+b1); h=silu(h@W2+b2); out=log_softmax(h@W3+b3)
// Register-chained activations (C-frag == A-frag identity), cp.async
// double-buffered weights, software-pipelined B ldmatrix (prefetch kt+1).
// bf16 hi/lo 3-term split (AhiBhi + AhiBlo + AloBhi), fp32 accumulate.
// 320 threads (10 warps) x 16 rows = 160 rows/block; grid 1250 (exact).
// ============================================================================

#define N_NODES 200000
#define DF      128
#define NC      40
#define THREADS 320
#define MB      160
#define NBLOCKS (N_NODES / MB)              // 1250, exact

#define SP 136                              // padded row stride (bf16 elems)
#define IMG_BYTES  (2 * 128 * SP * 2)       // 69632: one layer image (hi+lo)
#define LAYER_U4   (IMG_BYTES / 16)         // 4352
#define HALF_BYTES (128 * SP * 2)           // 34816: lo offset inside image
#define SMEM_TOTAL (2 * IMG_BYTES)          // 139264: double-buffered weights

// Prepped weights: per layer, [n:128][k:SP] bf16 hi then lo. L3 rows 40..127=0.
__device__ uint4 g_Wp4[4 * LAYER_U4];

__device__ __forceinline__ uint32_t s2u(const void* p) {
    uint32_t a;
    asm("{ .reg .u64 t; cvta.to.shared.u64 t, %1; cvt.u32.u64 %0, t; }" : "=r"(a) : "l"(p));
    return a;
}

#define LDSM4(r0, r1, r2, r3, a) \
    asm volatile("ldmatrix.sync.aligned.m8n8.x4.shared.b16 {%0,%1,%2,%3}, [%4];" \
                 : "=r"(r0), "=r"(r1), "=r"(r2), "=r"(r3) : "r"(a))
#define LDSM2(r0, r1, a) \
    asm volatile("ldmatrix.sync.aligned.m8n8.x2.shared.b16 {%0,%1}, [%2];" \
                 : "=r"(r0), "=r"(r1) : "r"(a))
#define MMA(c0, c1, c2, c3, a0, a1, a2, a3, b0, b1) \
    asm volatile("mma.sync.aligned.m16n8k16.row.col.f32.bf16.bf16.f32 " \
                 "{%0,%1,%2,%3}, {%4,%5,%6,%7}, {%8,%9}, {%0,%1,%2,%3};" \
                 : "+f"(c0), "+f"(c1), "+f"(c2), "+f"(c3) \
                 : "r"(a0), "r"(a1), "r"(a2), "r"(a3), "r"(b0), "r"(b1))

#define CP_ASYNC16(dst, src) \
    asm volatile("cp.async.cg.shared.global [%0], [%1], 16;" \
                 :: "r"(dst), "l"(src) : "memory")
#define CP_COMMIT() asm volatile("cp.async.commit_group;" ::: "memory")
#define CP_WAIT1()  asm volatile("cp.async.wait_group 1;" ::: "memory")
#define CP_WAIT0()  asm volatile("cp.async.wait_group 0;" ::: "memory")

__device__ __forceinline__ uint32_t pkb(__nv_bfloat16 a, __nv_bfloat16 b) {
    return (uint32_t)__bfloat16_as_ushort(a) | ((uint32_t)__bfloat16_as_ushort(b) << 16);
}
__device__ __forceinline__ void split2(float a, float b, uint32_t& hi, uint32_t& lo) {
    __nv_bfloat16 ha = __float2bfloat16_rn(a), hb = __float2bfloat16_rn(b);
    hi = pkb(ha, hb);
    lo = pkb(__float2bfloat16_rn(a - __bfloat162float(ha)),
             __float2bfloat16_rn(b - __bfloat162float(hb)));
}
__device__ __forceinline__ float silu_f(float v) {
    return __fdividef(v, 1.0f + __expf(-v));
}

// ============================================================================
// Prep: W[k][n] -> padded [n][SP] bf16 hi/lo images (layer 3 zero-padded)
// ============================================================================
__global__ __launch_bounds__(256)
void prep_weights(const float* __restrict__ W0, const float* __restrict__ W1,
                  const float* __restrict__ W2, const float* __restrict__ W3) {
    int e = blockIdx.x * 256 + threadIdx.x;        // over 4*128*128
    if (e >= 4 * 128 * 128) return;
    int l = e >> 14, r = e & 16383, n = r >> 7, k = r & 127;
    float v;
    if (l < 3) {
        const float* W = (l == 0) ? W0 : ((l == 1) ? W1 : W2);
        v = W[k * 128 + n];
    } else {
        v = (n < NC) ? W3[k * NC + n] : 0.0f;
    }
    __nv_bfloat16* gw = (__nv_bfloat16*)g_Wp4;
    size_t base = (size_t)l * (2 * 128 * SP);
    __nv_bfloat16 h = __float2bfloat16_rn(v);
    gw[base + n * SP + k] = h;
    gw[base + 128 * SP + n * SP + k] = __float2bfloat16_rn(v - __bfloat162float(h));
}

// async-copy one layer image into a smem buffer
__device__ __forceinline__ void cpasync_layer(uint32_t dst, int layer, int tid) {
    const uint4* src = g_Wp4 + (size_t)layer * LAYER_U4;
    for (int i = tid; i < LAYER_U4; i += THREADS)
        CP_ASYNC16(dst + (uint32_t)i * 16, src + i);
    CP_COMMIT();
}

// one hidden layer: A(hi/lo regs) x B(smem, pipelined LDSM) -> silu -> next A
__device__ __forceinline__ void hidden_layer(
    const uint32_t Ahi[8][4], const uint32_t Alo[8][4],
    uint32_t nAhi[8][4], uint32_t nAlo[8][4],
    uint32_t bufbase, const float* __restrict__ bias,
    uint32_t ofsB, int q)
{
    uint32_t Bh[2][4], Bl[2][4];
    const uint32_t base = bufbase + ofsB;
    // prologue: prefetch (p=0, kt=0)
    LDSM4(Bh[0][0], Bh[0][1], Bh[0][2], Bh[0][3], base);
    LDSM4(Bl[0][0], Bl[0][1], Bl[0][2], Bl[0][3], base + HALF_BYTES);
#pragma unroll
    for (int p = 0; p < 8; p++) {              // n-tile pairs (cols 16p..16p+15)
        const float2 bA = __ldg((const float2*)(bias + 16 * p + 2 * q));
        const float2 bB = __ldg((const float2*)(bias + 16 * p + 8 + 2 * q));
        float c0 = bA.x, c1 = bA.y, c2 = bA.x, c3 = bA.y;
        float c4 = bB.x, c5 = bB.y, c6 = bB.x, c7 = bB.y;
#pragma unroll
        for (int kt = 0; kt < 8; kt++) {
            const int g = p * 8 + kt;
            const int cur = g & 1, nxt = cur ^ 1;
            if (g < 63) {                      // prefetch next (p,kt)
                const uint32_t na = base +
                    (uint32_t)((((g + 1) >> 3) * (16 * SP * 2)) + (((g + 1) & 7) * 32));
                LDSM4(Bh[nxt][0], Bh[nxt][1], Bh[nxt][2], Bh[nxt][3], na);
                LDSM4(Bl[nxt][0], Bl[nxt][1], Bl[nxt][2], Bl[nxt][3], na + HALF_BYTES);
            }
            MMA(c0, c1, c2, c3, Ahi[kt][0], Ahi[kt][1], Ahi[kt][2], Ahi[kt][3], Bh[cur][0], Bh[cur][1]);
            MMA(c4, c5, c6, c7, Ahi[kt][0], Ahi[kt][1], Ahi[kt][2], Ahi[kt][3], Bh[cur][2], Bh[cur][3]);
            MMA(c0, c1, c2, c3, Ahi[kt][0], Ahi[kt][1], Ahi[kt][2], Ahi[kt][3], Bl[cur][0], Bl[cur][1]);
            MMA(c4, c5, c6, c7, Ahi[kt][0], Ahi[kt][1], Ahi[kt][2], Ahi[kt][3], Bl[cur][2], Bl[cur][3]);
            MMA(c0, c1, c2, c3, Alo[kt][0], Alo[kt][1], Alo[kt][2], Alo[kt][3], Bh[cur][0], Bh[cur][1]);
            MMA(c4, c5, c6, c7, Alo[kt][0], Alo[kt][1], Alo[kt][2], Alo[kt][3], Bh[cur][2], Bh[cur][3]);
        }
        // C-frag == A-frag: silu + hi/lo split -> next layer k-tile p fragments
        split2(silu_f(c0), silu_f(c1), nAhi[p][0], nAlo[p][0]);
        split2(silu_f(c2), silu_f(c3), nAhi[p][1], nAlo[p][1]);
        split2(silu_f(c4), silu_f(c5), nAhi[p][2], nAlo[p][2]);
        split2(silu_f(c6), silu_f(c7), nAhi[p][3], nAlo[p][3]);
    }
}

// ============================================================================
// Main kernel
// ============================================================================
__global__ __launch_bounds__(THREADS)
void chebnet_mma_kernel(
    const float* __restrict__ x,
    const float* __restrict__ b0, const float* __restrict__ b1,
    const float* __restrict__ b2, const float* __restrict__ b3,
    float* __restrict__ out)
{
    extern __shared__ char sm[];
    const uint32_t smb = s2u(sm);
    const int tid  = threadIdx.x;
    const int lane = tid & 31;
    const int warp = tid >> 5;
    const int row0 = blockIdx.x * MB + warp * 16;   // this warp's 16 rows
    const int r    = lane >> 2;        // 0..7
    const int q    = lane & 3;

    const uint32_t ofsB = ((uint32_t)(((lane & 7) + ((lane & 16) >> 1)) * SP) * 2) + ((lane & 8) * 2);

    // ---- prefetch weights: L0 -> buf0 (G0), L1 -> buf1 (G1) ----
    cpasync_layer(smb, 0, tid);
    cpasync_layer(smb + IMG_BYTES, 1, tid);

    // ---- load x directly into A fragments (no bounds checks: grid exact) ----
    uint32_t Ah[8][4], Al[8][4], Nh[8][4], Nl[8][4];
    {
        const float* xr0 = x + (size_t)(row0 + r) * DF;
        const float* xr8 = x + (size_t)(row0 + r + 8) * DF;
#pragma unroll
        for (int kt = 0; kt < 8; kt++) {
            const int c = kt * 16 + 2 * q;
            float2 e0 = *(const float2*)(xr0 + c);
            float2 e1 = *(const float2*)(xr8 + c);
            float2 e2 = *(const float2*)(xr0 + c + 8);
            float2 e3 = *(const float2*)(xr8 + c + 8);
            split2(e0.x, e0.y, Ah[kt][0], Al[kt][0]);
            split2(e1.x, e1.y, Ah[kt][1], Al[kt][1]);
            split2(e2.x, e2.y, Ah[kt][2], Al[kt][2]);
            split2(e3.x, e3.y, Ah[kt][3], Al[kt][3]);
        }
    }

    // ---- hidden layers 0..2 (rolled; buffers alternate; prefetch l+2) ----
    for (int l = 0; l < 3; l++) {
        CP_WAIT1();                            // this layer's image landed
        __syncthreads();
        const float* bias = (l == 0) ? b0 : ((l == 1) ? b1 : b2);
        hidden_layer(Ah, Al, Nh, Nl, smb + (uint32_t)(l & 1) * IMG_BYTES, bias, ofsB, q);
        __syncthreads();                       // all warps done reading buffer
        if (l < 2)
            cpasync_layer(smb + (uint32_t)(l & 1) * IMG_BYTES, l + 2, tid);
#pragma unroll
        for (int i = 0; i < 8; i++)
#pragma unroll
            for (int j = 0; j < 4; j++) { Ah[i][j] = Nh[i][j]; Al[i][j] = Nl[i][j]; }
    }

    // ---- output layer (buf1): N=40 ----
    CP_WAIT0();                 // G3 (L3) landed
    __syncthreads();
    {
        const uint32_t bufb = smb + IMG_BYTES;
        float lgA[10], lgB[10];            // rows r and r+8, 10 cols each
#pragma unroll
        for (int p = 0; p < 2; p++) {      // n-tiles 0..3 (cols 0..31)
            const float2 bA = __ldg((const float2*)(b3 + 16 * p + 2 * q));
            const float2 bB = __ldg((const float2*)(b3 + 16 * p + 8 + 2 * q));
            float c0 = bA.x, c1 = bA.y, c2 = bA.x, c3 = bA.y;
            float c4 = bB.x, c5 = bB.y, c6 = bB.x, c7 = bB.y;
            const uint32_t pb = bufb + (uint32_t)(p * 16 * SP) * 2 + ofsB;
#pragma unroll
            for (int kt = 0; kt < 8; kt++) {
                const uint32_t ba = pb + kt * 32;
                uint32_t h0, h1, h2, h3, l0, l1, l2, l3;
                LDSM4(h0, h1, h2, h3, ba);
                LDSM4(l0, l1, l2, l3, ba + HALF_BYTES);
                MMA(c0, c1, c2, c3, Ah[kt][0], Ah[kt][1], Ah[kt][2], Ah[kt][3], h0, h1);
                MMA(c4, c5, c6, c7, Ah[kt][0], Ah[kt][1], Ah[kt][2], Ah[kt][3], h2, h3);
                MMA(c0, c1, c2, c3, Ah[kt][0], Ah[kt][1], Ah[kt][2], Ah[kt][3], l0, l1);
                MMA(c4, c5, c6, c7, Ah[kt][0], Ah[kt][1], Ah[kt][2], Ah[kt][3], l2, l3);
                MMA(c0, c1, c2, c3, Al[kt][0], Al[kt][1], Al[kt][2], Al[kt][3], h0, h1);
                MMA(c4, c5, c6, c7, Al[kt][0], Al[kt][1], Al[kt][2], Al[kt][3], h2, h3);
            }
            lgA[4 * p + 0] = c0; lgA[4 * p + 1] = c1; lgB[4 * p + 0] = c2; lgB[4 * p + 1] = c3;
            lgA[4 * p + 2] = c4; lgA[4 * p + 3] = c5; lgB[4 * p + 2] = c6; lgB[4 * p + 3] = c7;
        }
        {   // n-tile 4 (cols 32..39)
            const float2 bA = __ldg((const float2*)(b3 + 32 + 2 * q));
            float c0 = bA.x, c1 = bA.y, c2 = bA.x, c3 = bA.y;
            const int r2 = lane & 15;
            const uint32_t cb = bufb + (uint32_t)((32 + (r2 & 7)) * SP) * 2 + (r2 & 8) * 2;
#pragma unroll
            for (int kt = 0; kt < 8; kt++) {
                const uint32_t ba = cb + kt * 32;
                uint32_t h0, h1, l0, l1;
                LDSM2(h0, h1, ba);
                LDSM2(l0, l1, ba + HALF_BYTES);
                MMA(c0, c1, c2, c3, Ah[kt][0], Ah[kt][1], Ah[kt][2], Ah[kt][3], h0, h1);
                MMA(c0, c1, c2, c3, Ah[kt][0], Ah[kt][1], Ah[kt][2], Ah[kt][3], l0, l1);
                MMA(c0, c1, c2, c3, Al[kt][0], Al[kt][1], Al[kt][2], Al[kt][3], h0, h1);
            }
            lgA[8] = c0; lgA[9] = c1; lgB[8] = c2; lgB[9] = c3;
        }

        // ---- log-softmax: quad reduction (lanes differing in bits 0,1) ----
        float mA = lgA[0], mB = lgB[0];
#pragma unroll
        for (int i = 1; i < 10; i++) { mA = fmaxf(mA, lgA[i]); mB = fmaxf(mB, lgB[i]); }
        mA = fmaxf(mA, __shfl_xor_sync(0xFFFFFFFF, mA, 1));
        mA = fmaxf(mA, __shfl_xor_sync(0xFFFFFFFF, mA, 2));
        mB = fmaxf(mB, __shfl_xor_sync(0xFFFFFFFF, mB, 1));
        mB = fmaxf(mB, __shfl_xor_sync(0xFFFFFFFF, mB, 2));
        float sA = 0.f, sB = 0.f;
#pragma unroll
        for (int i = 0; i < 10; i++) { sA += __expf(lgA[i] - mA); sB += __expf(lgB[i] - mB); }
        sA += __shfl_xor_sync(0xFFFFFFFF, sA, 1);
        sA += __shfl_xor_sync(0xFFFFFFFF, sA, 2);
        sB += __shfl_xor_sync(0xFFFFFFFF, sB, 1);
        sB += __shfl_xor_sync(0xFFFFFFFF, sB, 2);
        const float lseA = mA + __logf(sA);
        const float lseB = mB + __logf(sB);

        float* oA = out + (size_t)(row0 + r) * NC + 2 * q;
        float* oB = out + (size_t)(row0 + r + 8) * NC + 2 * q;
#pragma unroll
        for (int nt = 0; nt < 5; nt++) {
            *(float2*)(oA + 8 * nt) = make_float2(lgA[2 * nt] - lseA, lgA[2 * nt + 1] - lseA);
            *(float2*)(oB + 8 * nt) = make_float2(lgB[2 * nt] - lseB, lgB[2 * nt + 1] - lseB);
        }
    }
}

// ============================================================================
// Inputs: x, edge_index(dead), W0,b0, W1,b1, W2,b2, W3,b3
// ============================================================================
extern "C" void kernel_launch(void* const* d_in, const int* in_sizes, int n_in,
                              void* d_out, int out_size)
{
    (void)in_sizes; (void)n_in; (void)out_size;
    const float* x  = (const float*)d_in[0];
    const float* W0 = (const float*)d_in[2];
    const float* b0 = (const float*)d_in[3];
    const float* W1 = (const float*)d_in[4];
    const float* b1 = (const float*)d_in[5];
    const float* W2 = (const float*)d_in[6];
    const float* b2 = (const float*)d_in[7];
    const float* W3 = (const float*)d_in[8];
    const float* b3 = (const float*)d_in[9];
    float* out = (float*)d_out;

    cudaFuncSetAttribute(chebnet_mma_kernel,
                         cudaFuncAttributeMaxDynamicSharedMemorySize, SMEM_TOTAL);

    prep_weights<<<(4 * 128 * 128) / 256, 256>>>(W0, W1, W2, W3);
    chebnet_mma_kernel<<<NBLOCKS, THREADS, SMEM_TOTAL>>>(x, b0, b1, b2, b3, out);
}

// round 13
// speedup vs baseline: 1.5869x; 1.5869x over previous
#include <cuda_runtime.h>
#include <cuda_fp16.h>
#include <cstdint>

// ============================================================================
// ChebConvNet fused MLP via mma.sync (HMMA fp16, baseline PTX).
//   h=silu(x@W0+b0); h=silu(h@W1+b1); h=silu(h@W2+b2); out=log_softmax(h@W3+b3)
// Register-chained activations (C-frag == A-frag identity), cp.async
// double-buffered weights.
// Precision: A single fp16 (2^-12), B split fp16 hi/lo (exact to 2^-24),
// 2-term A*Bhi + A*Blo, fp32 accumulate -> 4 MMAs per (p,kt) instead of 6,
// and A-lo registers eliminated -> 512 threads (16 warps, 4/SMSP).
// 16 rows/warp, MB=256, grid 782 (last block partially OOB: clamped loads,
// guarded stores).
// ============================================================================

#define N_NODES 200000
#define DF      128
#define NC      40
#define THREADS 512
#define MB      256
#define NBLOCKS ((N_NODES + MB - 1) / MB)   // 782

#define SP 136                              // padded row stride (fp16 elems)
#define IMG_BYTES  (2 * 128 * SP * 2)       // 69632: one layer image (hi+lo)
#define LAYER_U4   (IMG_BYTES / 16)         // 4352
#define HALF_BYTES (128 * SP * 2)           // 34816: lo offset inside image
#define SMEM_TOTAL (2 * IMG_BYTES)          // 139264: double-buffered weights

// Prepped weights: per layer, [n:128][k:SP] fp16 hi then lo. L3 rows 40..127=0.
__device__ uint4 g_Wp4[4 * LAYER_U4];

__device__ __forceinline__ uint32_t s2u(const void* p) {
    uint32_t a;
    asm("{ .reg .u64 t; cvta.to.shared.u64 t, %1; cvt.u32.u64 %0, t; }" : "=r"(a) : "l"(p));
    return a;
}

#define LDSM4(r0, r1, r2, r3, a) \
    asm volatile("ldmatrix.sync.aligned.m8n8.x4.shared.b16 {%0,%1,%2,%3}, [%4];" \
                 : "=r"(r0), "=r"(r1), "=r"(r2), "=r"(r3) : "r"(a))
#define LDSM2(r0, r1, a) \
    asm volatile("ldmatrix.sync.aligned.m8n8.x2.shared.b16 {%0,%1}, [%2];" \
                 : "=r"(r0), "=r"(r1) : "r"(a))
#define MMA(c0, c1, c2, c3, a0, a1, a2, a3, b0, b1) \
    asm volatile("mma.sync.aligned.m16n8k16.row.col.f32.f16.f16.f32 " \
                 "{%0,%1,%2,%3}, {%4,%5,%6,%7}, {%8,%9}, {%0,%1,%2,%3};" \
                 : "+f"(c0), "+f"(c1), "+f"(c2), "+f"(c3) \
                 : "r"(a0), "r"(a1), "r"(a2), "r"(a3), "r"(b0), "r"(b1))

#define CP_ASYNC16(dst, src) \
    asm volatile("cp.async.cg.shared.global [%0], [%1], 16;" \
                 :: "r"(dst), "l"(src) : "memory")
#define CP_COMMIT() asm volatile("cp.async.commit_group;" ::: "memory")
#define CP_WAIT1()  asm volatile("cp.async.wait_group 1;" ::: "memory")
#define CP_WAIT0()  asm volatile("cp.async.wait_group 0;" ::: "memory")

__device__ __forceinline__ uint32_t pk2h(float a, float b) {
    __half2 h = __floats2half2_rn(a, b);        // low = a, high = b
    return *(uint32_t*)&h;
}
__device__ __forceinline__ float silu_f(float v) {
    return __fdividef(v, 1.0f + __expf(-v));
}

// ============================================================================
// Prep: W[k][n] -> padded [n][SP] fp16 hi/lo images (layer 3 zero-padded)
// ============================================================================
__global__ __launch_bounds__(256)
void prep_weights(const float* __restrict__ W0, const float* __restrict__ W1,
                  const float* __restrict__ W2, const float* __restrict__ W3) {
    int e = blockIdx.x * 256 + threadIdx.x;        // over 4*128*128
    if (e >= 4 * 128 * 128) return;
    int l = e >> 14, r = e & 16383, n = r >> 7, k = r & 127;
    float v;
    if (l < 3) {
        const float* W = (l == 0) ? W0 : ((l == 1) ? W1 : W2);
        v = W[k * 128 + n];
    } else {
        v = (n < NC) ? W3[k * NC + n] : 0.0f;
    }
    __half* gw = (__half*)g_Wp4;
    size_t base = (size_t)l * (2 * 128 * SP);
    __half h = __float2half_rn(v);
    gw[base + n * SP + k] = h;
    gw[base + 128 * SP + n * SP + k] = __float2half_rn(v - __half2float(h));
}

// async-copy one layer image into a smem buffer
__device__ __forceinline__ void cpasync_layer(uint32_t dst, int layer, int tid) {
    const uint4* src = g_Wp4 + (size_t)layer * LAYER_U4;
    for (int i = tid; i < LAYER_U4; i += THREADS)
        CP_ASYNC16(dst + (uint32_t)i * 16, src + i);
    CP_COMMIT();
}

// one hidden layer: A(fp16 regs) x (Bhi+Blo)(smem) -> silu -> next A (fp16 regs)
__device__ __forceinline__ void hidden_layer(
    const uint32_t Ah[8][4], uint32_t nAh[8][4],
    uint32_t bufbase, const float* __restrict__ bias,
    uint32_t ofsB, int q)
{
#pragma unroll
    for (int p = 0; p < 8; p++) {              // n-tile pairs (cols 16p..16p+15)
        const float2 bA = __ldg((const float2*)(bias + 16 * p + 2 * q));
        const float2 bB = __ldg((const float2*)(bias + 16 * p + 8 + 2 * q));
        float c0 = bA.x, c1 = bA.y, c2 = bA.x, c3 = bA.y;
        float c4 = bB.x, c5 = bB.y, c6 = bB.x, c7 = bB.y;
        const uint32_t pb = bufbase + (uint32_t)(p * 16 * SP) * 2 + ofsB;
#pragma unroll
        for (int kt = 0; kt < 8; kt++) {
            const uint32_t ba = pb + kt * 32;
            uint32_t h0, h1, h2, h3, l0, l1, l2, l3;
            LDSM4(h0, h1, h2, h3, ba);
            LDSM4(l0, l1, l2, l3, ba + HALF_BYTES);
            MMA(c0, c1, c2, c3, Ah[kt][0], Ah[kt][1], Ah[kt][2], Ah[kt][3], h0, h1);
            MMA(c4, c5, c6, c7, Ah[kt][0], Ah[kt][1], Ah[kt][2], Ah[kt][3], h2, h3);
            MMA(c0, c1, c2, c3, Ah[kt][0], Ah[kt][1], Ah[kt][2], Ah[kt][3], l0, l1);
            MMA(c4, c5, c6, c7, Ah[kt][0], Ah[kt][1], Ah[kt][2], Ah[kt][3], l2, l3);
        }
        // C-frag == A-frag: silu + fp16 pack -> next layer k-tile p fragments
        nAh[p][0] = pk2h(silu_f(c0), silu_f(c1));
        nAh[p][1] = pk2h(silu_f(c2), silu_f(c3));
        nAh[p][2] = pk2h(silu_f(c4), silu_f(c5));
        nAh[p][3] = pk2h(silu_f(c6), silu_f(c7));
    }
}

// ============================================================================
// Main kernel
// ============================================================================
__global__ __launch_bounds__(THREADS)
void chebnet_mma_kernel(
    const float* __restrict__ x,
    const float* __restrict__ b0, const float* __restrict__ b1,
    const float* __restrict__ b2, const float* __restrict__ b3,
    float* __restrict__ out)
{
    extern __shared__ char sm[];
    const uint32_t smb = s2u(sm);
    const int tid  = threadIdx.x;
    const int lane = tid & 31;
    const int warp = tid >> 5;
    const int row0 = blockIdx.x * MB + warp * 16;   // this warp's 16 rows
    const int r    = lane >> 2;        // 0..7
    const int q    = lane & 3;

    const uint32_t ofsB = ((uint32_t)(((lane & 7) + ((lane & 16) >> 1)) * SP) * 2) + ((lane & 8) * 2);

    // ---- prefetch weights: L0 -> buf0 (G0), L1 -> buf1 (G1) ----
    cpasync_layer(smb, 0, tid);
    cpasync_layer(smb + IMG_BYTES, 1, tid);

    // ---- load x directly into A fragments (clamped rows for last block) ----
    const int rA = row0 + r, rB = row0 + r + 8;
    const int rAc = (rA < N_NODES) ? rA : (N_NODES - 1);
    const int rBc = (rB < N_NODES) ? rB : (N_NODES - 1);
    uint32_t Ah[8][4], Nh[8][4];
    {
        const float* xr0 = x + (size_t)rAc * DF;
        const float* xr8 = x + (size_t)rBc * DF;
#pragma unroll
        for (int kt = 0; kt < 8; kt++) {
            const int c = kt * 16 + 2 * q;
            float2 e0 = *(const float2*)(xr0 + c);
            float2 e1 = *(const float2*)(xr8 + c);
            float2 e2 = *(const float2*)(xr0 + c + 8);
            float2 e3 = *(const float2*)(xr8 + c + 8);
            Ah[kt][0] = pk2h(e0.x, e0.y);
            Ah[kt][1] = pk2h(e1.x, e1.y);
            Ah[kt][2] = pk2h(e2.x, e2.y);
            Ah[kt][3] = pk2h(e3.x, e3.y);
        }
    }

    // ---- hidden layers 0..2 (rolled; buffers alternate; prefetch l+2) ----
    for (int l = 0; l < 3; l++) {
        CP_WAIT1();                            // this layer's image landed
        __syncthreads();
        const float* bias = (l == 0) ? b0 : ((l == 1) ? b1 : b2);
        hidden_layer(Ah, Nh, smb + (uint32_t)(l & 1) * IMG_BYTES, bias, ofsB, q);
        __syncthreads();                       // all warps done reading buffer
        if (l < 2)
            cpasync_layer(smb + (uint32_t)(l & 1) * IMG_BYTES, l + 2, tid);
#pragma unroll
        for (int i = 0; i < 8; i++)
#pragma unroll
            for (int j = 0; j < 4; j++) Ah[i][j] = Nh[i][j];
    }

    // ---- output layer (buf1): N=40 ----
    CP_WAIT0();                 // G3 (L3) landed
    __syncthreads();
    {
        const uint32_t bufb = smb + IMG_BYTES;
        float lgA[10], lgB[10];            // rows r and r+8, 10 cols each
#pragma unroll
        for (int p = 0; p < 2; p++) {      // n-tiles 0..3 (cols 0..31)
            const float2 bA = __ldg((const float2*)(b3 + 16 * p + 2 * q));
            const float2 bB = __ldg((const float2*)(b3 + 16 * p + 8 + 2 * q));
            float c0 = bA.x, c1 = bA.y, c2 = bA.x, c3 = bA.y;
            float c4 = bB.x, c5 = bB.y, c6 = bB.x, c7 = bB.y;
            const uint32_t pb = bufb + (uint32_t)(p * 16 * SP) * 2 + ofsB;
#pragma unroll
            for (int kt = 0; kt < 8; kt++) {
                const uint32_t ba = pb + kt * 32;
                uint32_t h0, h1, h2, h3, l0, l1, l2, l3;
                LDSM4(h0, h1, h2, h3, ba);
                LDSM4(l0, l1, l2, l3, ba + HALF_BYTES);
                MMA(c0, c1, c2, c3, Ah[kt][0], Ah[kt][1], Ah[kt][2], Ah[kt][3], h0, h1);
                MMA(c4, c5, c6, c7, Ah[kt][0], Ah[kt][1], Ah[kt][2], Ah[kt][3], h2, h3);
                MMA(c0, c1, c2, c3, Ah[kt][0], Ah[kt][1], Ah[kt][2], Ah[kt][3], l0, l1);
                MMA(c4, c5, c6, c7, Ah[kt][0], Ah[kt][1], Ah[kt][2], Ah[kt][3], l2, l3);
            }
            lgA[4 * p + 0] = c0; lgA[4 * p + 1] = c1; lgB[4 * p + 0] = c2; lgB[4 * p + 1] = c3;
            lgA[4 * p + 2] = c4; lgA[4 * p + 3] = c5; lgB[4 * p + 2] = c6; lgB[4 * p + 3] = c7;
        }
        {   // n-tile 4 (cols 32..39)
            const float2 bA = __ldg((const float2*)(b3 + 32 + 2 * q));
            float c0 = bA.x, c1 = bA.y, c2 = bA.x, c3 = bA.y;
            const int r2 = lane & 15;
            const uint32_t cb = bufb + (uint32_t)((32 + (r2 & 7)) * SP) * 2 + (r2 & 8) * 2;
#pragma unroll
            for (int kt = 0; kt < 8; kt++) {
                const uint32_t ba = cb + kt * 32;
                uint32_t h0, h1, l0, l1;
                LDSM2(h0, h1, ba);
                LDSM2(l0, l1, ba + HALF_BYTES);
                MMA(c0, c1, c2, c3, Ah[kt][0], Ah[kt][1], Ah[kt][2], Ah[kt][3], h0, h1);
                MMA(c0, c1, c2, c3, Ah[kt][0], Ah[kt][1], Ah[kt][2], Ah[kt][3], l0, l1);
            }
            lgA[8] = c0; lgA[9] = c1; lgB[8] = c2; lgB[9] = c3;
        }

        // ---- log-softmax: quad reduction (lanes differing in bits 0,1) ----
        float mA = lgA[0], mB = lgB[0];
#pragma unroll
        for (int i = 1; i < 10; i++) { mA = fmaxf(mA, lgA[i]); mB = fmaxf(mB, lgB[i]); }
        mA = fmaxf(mA, __shfl_xor_sync(0xFFFFFFFF, mA, 1));
        mA = fmaxf(mA, __shfl_xor_sync(0xFFFFFFFF, mA, 2));
        mB = fmaxf(mB, __shfl_xor_sync(0xFFFFFFFF, mB, 1));
        mB = fmaxf(mB, __shfl_xor_sync(0xFFFFFFFF, mB, 2));
        float sA = 0.f, sB = 0.f;
#pragma unroll
        for (int i = 0; i < 10; i++) { sA += __expf(lgA[i] - mA); sB += __expf(lgB[i] - mB); }
        sA += __shfl_xor_sync(0xFFFFFFFF, sA, 1);
        sA += __shfl_xor_sync(0xFFFFFFFF, sA, 2);
        sB += __shfl_xor_sync(0xFFFFFFFF, sB, 1);
        sB += __shfl_xor_sync(0xFFFFFFFF, sB, 2);
        const float lseA = mA + __logf(sA);
        const float lseB = mB + __logf(sB);

        if (rA < N_NODES) {
            float* oA = out + (size_t)rA * NC + 2 * q;
#pragma unroll
            for (int nt = 0; nt < 5; nt++)
                *(float2*)(oA + 8 * nt) = make_float2(lgA[2 * nt] - lseA, lgA[2 * nt + 1] - lseA);
        }
        if (rB < N_NODES) {
            float* oB = out + (size_t)rB * NC + 2 * q;
#pragma unroll
            for (int nt = 0; nt < 5; nt++)
                *(float2*)(oB + 8 * nt) = make_float2(lgB[2 * nt] - lseB, lgB[2 * nt + 1] - lseB);
        }
    }
}

// ============================================================================
// Inputs: x, edge_index(dead), W0,b0, W1,b1, W2,b2, W3,b3
// ============================================================================
extern "C" void kernel_launch(void* const* d_in, const int* in_sizes, int n_in,
                              void* d_out, int out_size)
{
    (void)in_sizes; (void)n_in; (void)out_size;
    const float* x  = (const float*)d_in[0];
    const float* W0 = (const float*)d_in[2];
    const float* b0 = (const float*)d_in[3];
    const float* W1 = (const float*)d_in[4];
    const float* b1 = (const float*)d_in[5];
    const float* W2 = (const float*)d_in[6];
    const float* b2 = (const float*)d_in[7];
    const float* W3 = (const float*)d_in[8];
    const float* b3 = (const float*)d_in[9];
    float* out = (float*)d_out;

    cudaFuncSetAttribute(chebnet_mma_kernel,
                         cudaFuncAttributeMaxDynamicSharedMemorySize, SMEM_TOTAL);

    prep_weights<<<(4 * 128 * 128) / 256, 256>>>(W0, W1, W2, W3);
    chebnet_mma_kernel<<<NBLOCKS, THREADS, SMEM_TOTAL>>>(x, b0, b1, b2, b3, out);
}

// round 14
// speedup vs baseline: 1.6185x; 1.0199x over previous
#include <cuda_runtime.h>
#include <cuda_fp16.h>
#include <cstdint>

// ============================================================================
// ChebConvNet fused MLP via mma.sync (HMMA fp16, baseline PTX).
//   h=silu(x@W0+b0); h=silu(h@W1+b1); h=silu(h@W2+b2); out=log_softmax(h@W3+b3)
// 12 warps x 32 rows/warp (two 16-row sets, A register-resident for both):
// each B ldmatrix pair feeds 8 MMAs (4 independent accumulator chains) ->
// half the smem crossbar traffic of 16-row warps + deep MMA ILP.
// Precision: A single fp16, B split fp16 hi/lo, 2-term, fp32 accumulate.
// cp.async double-buffered weights; register-chained activations
// (C-frag == A-frag identity).
// ============================================================================

#define N_NODES 200000
#define DF      128
#define NC      40
#define THREADS 384
#define MB      384                          // 12 warps x 32 rows
#define NBLOCKS ((N_NODES + MB - 1) / MB)    // 521

#define SP 136                               // padded row stride (fp16 elems)
#define IMG_BYTES  (2 * 128 * SP * 2)        // 69632: one layer image (hi+lo)
#define LAYER_U4   (IMG_BYTES / 16)          // 4352
#define HALF_BYTES (128 * SP * 2)            // 34816: lo offset inside image
#define SMEM_TOTAL (2 * IMG_BYTES)           // 139264

// Prepped weights: per layer, [n:128][k:SP] fp16 hi then lo. L3 rows 40..127=0.
__device__ uint4 g_Wp4[4 * LAYER_U4];

__device__ __forceinline__ uint32_t s2u(const void* p) {
    uint32_t a;
    asm("{ .reg .u64 t; cvta.to.shared.u64 t, %1; cvt.u32.u64 %0, t; }" : "=r"(a) : "l"(p));
    return a;
}

#define LDSM4(r0, r1, r2, r3, a) \
    asm volatile("ldmatrix.sync.aligned.m8n8.x4.shared.b16 {%0,%1,%2,%3}, [%4];" \
                 : "=r"(r0), "=r"(r1), "=r"(r2), "=r"(r3) : "r"(a))
#define LDSM2(r0, r1, a) \
    asm volatile("ldmatrix.sync.aligned.m8n8.x2.shared.b16 {%0,%1}, [%2];" \
                 : "=r"(r0), "=r"(r1) : "r"(a))
#define MMA(c0, c1, c2, c3, a0, a1, a2, a3, b0, b1) \
    asm volatile("mma.sync.aligned.m16n8k16.row.col.f32.f16.f16.f32 " \
                 "{%0,%1,%2,%3}, {%4,%5,%6,%7}, {%8,%9}, {%0,%1,%2,%3};" \
                 : "+f"(c0), "+f"(c1), "+f"(c2), "+f"(c3) \
                 : "r"(a0), "r"(a1), "r"(a2), "r"(a3), "r"(b0), "r"(b1))

#define CP_ASYNC16(dst, src) \
    asm volatile("cp.async.cg.shared.global [%0], [%1], 16;" \
                 :: "r"(dst), "l"(src) : "memory")
#define CP_COMMIT() asm volatile("cp.async.commit_group;" ::: "memory")
#define CP_WAIT1()  asm volatile("cp.async.wait_group 1;" ::: "memory")
#define CP_WAIT0()  asm volatile("cp.async.wait_group 0;" ::: "memory")

__device__ __forceinline__ uint32_t pk2h(float a, float b) {
    __half2 h = __floats2half2_rn(a, b);         // low = a, high = b
    return *(uint32_t*)&h;
}
__device__ __forceinline__ float silu_f(float v) {
    return __fdividef(v, 1.0f + __expf(-v));
}

// ============================================================================
// Prep: W[k][n] -> padded [n][SP] fp16 hi/lo images (layer 3 zero-padded)
// ============================================================================
__global__ __launch_bounds__(256)
void prep_weights(const float* __restrict__ W0, const float* __restrict__ W1,
                  const float* __restrict__ W2, const float* __restrict__ W3) {
    int e = blockIdx.x * 256 + threadIdx.x;        // over 4*128*128
    if (e >= 4 * 128 * 128) return;
    int l = e >> 14, r = e & 16383, n = r >> 7, k = r & 127;
    float v;
    if (l < 3) {
        const float* W = (l == 0) ? W0 : ((l == 1) ? W1 : W2);
        v = W[k * 128 + n];
    } else {
        v = (n < NC) ? W3[k * NC + n] : 0.0f;
    }
    __half* gw = (__half*)g_Wp4;
    size_t base = (size_t)l * (2 * 128 * SP);
    __half h = __float2half_rn(v);
    gw[base + n * SP + k] = h;
    gw[base + 128 * SP + n * SP + k] = __float2half_rn(v - __half2float(h));
}

// async-copy one layer image into a smem buffer
__device__ __forceinline__ void cpasync_layer(uint32_t dst, int layer, int tid) {
    const uint4* src = g_Wp4 + (size_t)layer * LAYER_U4;
    for (int i = tid; i < LAYER_U4; i += THREADS)
        CP_ASYNC16(dst + (uint32_t)i * 16, src + i);
    CP_COMMIT();
}

// one hidden layer for BOTH row-sets: A(fp16 regs) x (Bhi+Blo) -> silu -> next A
__device__ __forceinline__ void hidden_layer(
    const uint32_t Ah[2][8][4], uint32_t Nh[2][8][4],
    uint32_t bufbase, const float* __restrict__ bias,
    uint32_t ofsB, int q)
{
#pragma unroll
    for (int p = 0; p < 8; p++) {              // n-tile pairs (cols 16p..16p+15)
        const float2 bA = __ldg((const float2*)(bias + 16 * p + 2 * q));
        const float2 bB = __ldg((const float2*)(bias + 16 * p + 8 + 2 * q));
        float c[2][8];
#pragma unroll
        for (int s = 0; s < 2; s++) {
            c[s][0] = bA.x; c[s][1] = bA.y; c[s][2] = bA.x; c[s][3] = bA.y;
            c[s][4] = bB.x; c[s][5] = bB.y; c[s][6] = bB.x; c[s][7] = bB.y;
        }
        const uint32_t pb = bufbase + (uint32_t)(p * 16 * SP) * 2 + ofsB;
#pragma unroll
        for (int kt = 0; kt < 8; kt++) {
            const uint32_t ba = pb + kt * 32;
            uint32_t h0, h1, h2, h3, l0, l1, l2, l3;
            LDSM4(h0, h1, h2, h3, ba);
            LDSM4(l0, l1, l2, l3, ba + HALF_BYTES);
            // 8 MMAs, 4 independent chains (s x n-half), dep distance 4
            MMA(c[0][0], c[0][1], c[0][2], c[0][3], Ah[0][kt][0], Ah[0][kt][1], Ah[0][kt][2], Ah[0][kt][3], h0, h1);
            MMA(c[0][4], c[0][5], c[0][6], c[0][7], Ah[0][kt][0], Ah[0][kt][1], Ah[0][kt][2], Ah[0][kt][3], h2, h3);
            MMA(c[1][0], c[1][1], c[1][2], c[1][3], Ah[1][kt][0], Ah[1][kt][1], Ah[1][kt][2], Ah[1][kt][3], h0, h1);
            MMA(c[1][4], c[1][5], c[1][6], c[1][7], Ah[1][kt][0], Ah[1][kt][1], Ah[1][kt][2], Ah[1][kt][3], h2, h3);
            MMA(c[0][0], c[0][1], c[0][2], c[0][3], Ah[0][kt][0], Ah[0][kt][1], Ah[0][kt][2], Ah[0][kt][3], l0, l1);
            MMA(c[0][4], c[0][5], c[0][6], c[0][7], Ah[0][kt][0], Ah[0][kt][1], Ah[0][kt][2], Ah[0][kt][3], l2, l3);
            MMA(c[1][0], c[1][1], c[1][2], c[1][3], Ah[1][kt][0], Ah[1][kt][1], Ah[1][kt][2], Ah[1][kt][3], l0, l1);
            MMA(c[1][4], c[1][5], c[1][6], c[1][7], Ah[1][kt][0], Ah[1][kt][1], Ah[1][kt][2], Ah[1][kt][3], l2, l3);
        }
        // C-frag == A-frag: silu + fp16 pack -> next layer k-tile p fragments
#pragma unroll
        for (int s = 0; s < 2; s++) {
            Nh[s][p][0] = pk2h(silu_f(c[s][0]), silu_f(c[s][1]));
            Nh[s][p][1] = pk2h(silu_f(c[s][2]), silu_f(c[s][3]));
            Nh[s][p][2] = pk2h(silu_f(c[s][4]), silu_f(c[s][5]));
            Nh[s][p][3] = pk2h(silu_f(c[s][6]), silu_f(c[s][7]));
        }
    }
}

// ============================================================================
// Main kernel
// ============================================================================
__global__ __launch_bounds__(THREADS)
void chebnet_mma_kernel(
    const float* __restrict__ x,
    const float* __restrict__ b0, const float* __restrict__ b1,
    const float* __restrict__ b2, const float* __restrict__ b3,
    float* __restrict__ out)
{
    extern __shared__ char sm[];
    const uint32_t smb = s2u(sm);
    const int tid  = threadIdx.x;
    const int lane = tid & 31;
    const int warp = tid >> 5;
    const int row0 = blockIdx.x * MB + warp * 32;   // this warp's 32 rows
    const int r    = lane >> 2;        // 0..7
    const int q    = lane & 3;

    const uint32_t ofsB = ((uint32_t)(((lane & 7) + ((lane & 16) >> 1)) * SP) * 2) + ((lane & 8) * 2);

    // ---- prefetch weights: L0 -> buf0 (G0), L1 -> buf1 (G1) ----
    cpasync_layer(smb, 0, tid);
    cpasync_layer(smb + IMG_BYTES, 1, tid);

    // ---- load x into A fragments for both sets (clamped rows, last block) ----
    uint32_t Ah[2][8][4], Nh[2][8][4];
#pragma unroll
    for (int s = 0; s < 2; s++) {
        const int rA = row0 + s * 16 + r;
        const int rB = rA + 8;
        const int rAc = (rA < N_NODES) ? rA : (N_NODES - 1);
        const int rBc = (rB < N_NODES) ? rB : (N_NODES - 1);
        const float* xr0 = x + (size_t)rAc * DF;
        const float* xr8 = x + (size_t)rBc * DF;
#pragma unroll
        for (int kt = 0; kt < 8; kt++) {
            const int c = kt * 16 + 2 * q;
            float2 e0 = *(const float2*)(xr0 + c);
            float2 e1 = *(const float2*)(xr8 + c);
            float2 e2 = *(const float2*)(xr0 + c + 8);
            float2 e3 = *(const float2*)(xr8 + c + 8);
            Ah[s][kt][0] = pk2h(e0.x, e0.y);
            Ah[s][kt][1] = pk2h(e1.x, e1.y);
            Ah[s][kt][2] = pk2h(e2.x, e2.y);
            Ah[s][kt][3] = pk2h(e3.x, e3.y);
        }
    }

    // ---- hidden layers 0..2 (rolled; buffers alternate; prefetch l+2) ----
    for (int l = 0; l < 3; l++) {
        CP_WAIT1();                            // this layer's image landed
        __syncthreads();
        const float* bias = (l == 0) ? b0 : ((l == 1) ? b1 : b2);
        hidden_layer(Ah, Nh, smb + (uint32_t)(l & 1) * IMG_BYTES, bias, ofsB, q);
        __syncthreads();                       // all warps done reading buffer
        if (l < 2)
            cpasync_layer(smb + (uint32_t)(l & 1) * IMG_BYTES, l + 2, tid);
#pragma unroll
        for (int s = 0; s < 2; s++)
#pragma unroll
            for (int i = 0; i < 8; i++)
#pragma unroll
                for (int j = 0; j < 4; j++) Ah[s][i][j] = Nh[s][i][j];
    }

    // ---- output layer (buf1): N=40, both sets ----
    CP_WAIT0();                 // G3 (L3) landed
    __syncthreads();
    {
        const uint32_t bufb = smb + IMG_BYTES;
        float lgA[2][10], lgB[2][10];      // per set: rows r and r+8, 10 cols
#pragma unroll
        for (int p = 0; p < 2; p++) {      // n-tiles 0..3 (cols 0..31)
            const float2 bA = __ldg((const float2*)(b3 + 16 * p + 2 * q));
            const float2 bB = __ldg((const float2*)(b3 + 16 * p + 8 + 2 * q));
            float c[2][8];
#pragma unroll
            for (int s = 0; s < 2; s++) {
                c[s][0] = bA.x; c[s][1] = bA.y; c[s][2] = bA.x; c[s][3] = bA.y;
                c[s][4] = bB.x; c[s][5] = bB.y; c[s][6] = bB.x; c[s][7] = bB.y;
            }
            const uint32_t pb = bufb + (uint32_t)(p * 16 * SP) * 2 + ofsB;
#pragma unroll
            for (int kt = 0; kt < 8; kt++) {
                const uint32_t ba = pb + kt * 32;
                uint32_t h0, h1, h2, h3, l0, l1, l2, l3;
                LDSM4(h0, h1, h2, h3, ba);
                LDSM4(l0, l1, l2, l3, ba + HALF_BYTES);
                MMA(c[0][0], c[0][1], c[0][2], c[0][3], Ah[0][kt][0], Ah[0][kt][1], Ah[0][kt][2], Ah[0][kt][3], h0, h1);
                MMA(c[0][4], c[0][5], c[0][6], c[0][7], Ah[0][kt][0], Ah[0][kt][1], Ah[0][kt][2], Ah[0][kt][3], h2, h3);
                MMA(c[1][0], c[1][1], c[1][2], c[1][3], Ah[1][kt][0], Ah[1][kt][1], Ah[1][kt][2], Ah[1][kt][3], h0, h1);
                MMA(c[1][4], c[1][5], c[1][6], c[1][7], Ah[1][kt][0], Ah[1][kt][1], Ah[1][kt][2], Ah[1][kt][3], h2, h3);
                MMA(c[0][0], c[0][1], c[0][2], c[0][3], Ah[0][kt][0], Ah[0][kt][1], Ah[0][kt][2], Ah[0][kt][3], l0, l1);
                MMA(c[0][4], c[0][5], c[0][6], c[0][7], Ah[0][kt][0], Ah[0][kt][1], Ah[0][kt][2], Ah[0][kt][3], l2, l3);
                MMA(c[1][0], c[1][1], c[1][2], c[1][3], Ah[1][kt][0], Ah[1][kt][1], Ah[1][kt][2], Ah[1][kt][3], l0, l1);
                MMA(c[1][4], c[1][5], c[1][6], c[1][7], Ah[1][kt][0], Ah[1][kt][1], Ah[1][kt][2], Ah[1][kt][3], l2, l3);
            }
#pragma unroll
            for (int s = 0; s < 2; s++) {
                lgA[s][4 * p + 0] = c[s][0]; lgA[s][4 * p + 1] = c[s][1];
                lgB[s][4 * p + 0] = c[s][2]; lgB[s][4 * p + 1] = c[s][3];
                lgA[s][4 * p + 2] = c[s][4]; lgA[s][4 * p + 3] = c[s][5];
                lgB[s][4 * p + 2] = c[s][6]; lgB[s][4 * p + 3] = c[s][7];
            }
        }
        {   // n-tile 4 (cols 32..39)
            const float2 bA = __ldg((const float2*)(b3 + 32 + 2 * q));
            float c[2][4];
#pragma unroll
            for (int s = 0; s < 2; s++) {
                c[s][0] = bA.x; c[s][1] = bA.y; c[s][2] = bA.x; c[s][3] = bA.y;
            }
            const int r2 = lane & 15;
            const uint32_t cb = bufb + (uint32_t)((32 + (r2 & 7)) * SP) * 2 + (r2 & 8) * 2;
#pragma unroll
            for (int kt = 0; kt < 8; kt++) {
                const uint32_t ba = cb + kt * 32;
                uint32_t h0, h1, l0, l1;
                LDSM2(h0, h1, ba);
                LDSM2(l0, l1, ba + HALF_BYTES);
                MMA(c[0][0], c[0][1], c[0][2], c[0][3], Ah[0][kt][0], Ah[0][kt][1], Ah[0][kt][2], Ah[0][kt][3], h0, h1);
                MMA(c[1][0], c[1][1], c[1][2], c[1][3], Ah[1][kt][0], Ah[1][kt][1], Ah[1][kt][2], Ah[1][kt][3], h0, h1);
                MMA(c[0][0], c[0][1], c[0][2], c[0][3], Ah[0][kt][0], Ah[0][kt][1], Ah[0][kt][2], Ah[0][kt][3], l0, l1);
                MMA(c[1][0], c[1][1], c[1][2], c[1][3], Ah[1][kt][0], Ah[1][kt][1], Ah[1][kt][2], Ah[1][kt][3], l0, l1);
            }
#pragma unroll
            for (int s = 0; s < 2; s++) {
                lgA[s][8] = c[s][0]; lgA[s][9] = c[s][1];
                lgB[s][8] = c[s][2]; lgB[s][9] = c[s][3];
            }
        }

        // ---- log-softmax + store, per set ----
#pragma unroll
        for (int s = 0; s < 2; s++) {
            float mA = lgA[s][0], mB = lgB[s][0];
#pragma unroll
            for (int i = 1; i < 10; i++) { mA = fmaxf(mA, lgA[s][i]); mB = fmaxf(mB, lgB[s][i]); }
            mA = fmaxf(mA, __shfl_xor_sync(0xFFFFFFFF, mA, 1));
            mA = fmaxf(mA, __shfl_xor_sync(0xFFFFFFFF, mA, 2));
            mB = fmaxf(mB, __shfl_xor_sync(0xFFFFFFFF, mB, 1));
            mB = fmaxf(mB, __shfl_xor_sync(0xFFFFFFFF, mB, 2));
            float sA = 0.f, sB = 0.f;
#pragma unroll
            for (int i = 0; i < 10; i++) {
                sA += __expf(lgA[s][i] - mA);
                sB += __expf(lgB[s][i] - mB);
            }
            sA += __shfl_xor_sync(0xFFFFFFFF, sA, 1);
            sA += __shfl_xor_sync(0xFFFFFFFF, sA, 2);
            sB += __shfl_xor_sync(0xFFFFFFFF, sB, 1);
            sB += __shfl_xor_sync(0xFFFFFFFF, sB, 2);
            const float lseA = mA + __logf(sA);
            const float lseB = mB + __logf(sB);

            const int rA = row0 + s * 16 + r;
            const int rB = rA + 8;
            if (rA < N_NODES) {
                float* oA = out + (size_t)rA * NC + 2 * q;
#pragma unroll
                for (int nt = 0; nt < 5; nt++)
                    *(float2*)(oA + 8 * nt) =
                        make_float2(lgA[s][2 * nt] - lseA, lgA[s][2 * nt + 1] - lseA);
            }
            if (rB < N_NODES) {
                float* oB = out + (size_t)rB * NC + 2 * q;
#pragma unroll
                for (int nt = 0; nt < 5; nt++)
                    *(float2*)(oB + 8 * nt) =
                        make_float2(lgB[s][2 * nt] - lseB, lgB[s][2 * nt + 1] - lseB);
            }
        }
    }
}

// ============================================================================
// Inputs: x, edge_index(dead), W0,b0, W1,b1, W2,b2, W3,b3
// ============================================================================
extern "C" void kernel_launch(void* const* d_in, const int* in_sizes, int n_in,
                              void* d_out, int out_size)
{
    (void)in_sizes; (void)n_in; (void)out_size;
    const float* x  = (const float*)d_in[0];
    const float* W0 = (const float*)d_in[2];
    const float* b0 = (const float*)d_in[3];
    const float* W1 = (const float*)d_in[4];
    const float* b1 = (const float*)d_in[5];
    const float* W2 = (const float*)d_in[6];
    const float* b2 = (const float*)d_in[7];
    const float* W3 = (const float*)d_in[8];
    const float* b3 = (const float*)d_in[9];
    float* out = (float*)d_out;

    cudaFuncSetAttribute(chebnet_mma_kernel,
                         cudaFuncAttributeMaxDynamicSharedMemorySize, SMEM_TOTAL);

    prep_weights<<<(4 * 128 * 128) / 256, 256>>>(W0, W1, W2, W3);
    chebnet_mma_kernel<<<NBLOCKS, THREADS, SMEM_TOTAL>>>(x, b0, b1, b2, b3, out);
}

// round 15
// speedup vs baseline: 1.8460x; 1.1406x over previous
#include <cuda_runtime.h>
#include <cuda_fp16.h>
#include <cstdint>

// ============================================================================
// ChebConvNet fused MLP via mma.sync (HMMA fp16, baseline PTX).
//   h=silu(x@W0+b0); h=silu(h@W1+b1); h=silu(h@W2+b2); out=log_softmax(h@W3+b3)
// 12 warps x 32 rows/warp, A register-resident (C-frag == A-frag chaining),
// fp16 2-term weight split (Bhi+Blo), fp32 accumulate.
// NEW: barrier-free layer pipeline -- 3 smem weight buffers, readiness via
// cp.async.mbarrier.arrive (hardware completion signal), buffer reuse via
// mbarrier arrive/wait. No __syncthreads in the main path, so warps free-run
// with ~1 layer of allowed skew and MUFU epilogues overlap MMA phases across
// warps instead of serializing at block barriers.
// ============================================================================

#define N_NODES 200000
#define DF      128
#define NC      40
#define THREADS 384
#define MB      384                          // 12 warps x 32 rows
#define NBLOCKS ((N_NODES + MB - 1) / MB)    // 521

#define SP 136                               // padded row stride (fp16 elems)
#define IMG_BYTES  (2 * 128 * SP * 2)        // 69632: one layer image (hi+lo)
#define LAYER_U4   (IMG_BYTES / 16)          // 4352
#define HALF_BYTES (128 * SP * 2)            // 34816: lo offset inside image
#define MBAR_OFF   (3 * IMG_BYTES)           // 208896
#define SMEM_TOTAL (MBAR_OFF + 64)           // 208960 (3 bufs + 4 mbarriers)

// Prepped weights: per layer, [n:128][k:SP] fp16 hi then lo. L3 rows 40..127=0.
__device__ uint4 g_Wp4[4 * LAYER_U4];

__device__ __forceinline__ uint32_t s2u(const void* p) {
    uint32_t a;
    asm("{ .reg .u64 t; cvta.to.shared.u64 t, %1; cvt.u32.u64 %0, t; }" : "=r"(a) : "l"(p));
    return a;
}

#define LDSM4(r0, r1, r2, r3, a) \
    asm volatile("ldmatrix.sync.aligned.m8n8.x4.shared.b16 {%0,%1,%2,%3}, [%4];" \
                 : "=r"(r0), "=r"(r1), "=r"(r2), "=r"(r3) : "r"(a))
#define LDSM2(r0, r1, a) \
    asm volatile("ldmatrix.sync.aligned.m8n8.x2.shared.b16 {%0,%1}, [%2];" \
                 : "=r"(r0), "=r"(r1) : "r"(a))
#define MMA(c0, c1, c2, c3, a0, a1, a2, a3, b0, b1) \
    asm volatile("mma.sync.aligned.m16n8k16.row.col.f32.f16.f16.f32 " \
                 "{%0,%1,%2,%3}, {%4,%5,%6,%7}, {%8,%9}, {%0,%1,%2,%3};" \
                 : "+f"(c0), "+f"(c1), "+f"(c2), "+f"(c3) \
                 : "r"(a0), "r"(a1), "r"(a2), "r"(a3), "r"(b0), "r"(b1))

#define CP_ASYNC16(dst, src) \
    asm volatile("cp.async.cg.shared.global [%0], [%1], 16;" \
                 :: "r"(dst), "l"(src) : "memory")

// mbarrier (baseline PTX; none of the sm_103a-gated tcgen05 path)
#define MBAR_INIT(mbar, cnt) \
    asm volatile("mbarrier.init.shared.b64 [%0], %1;" :: "r"(mbar), "r"(cnt) : "memory")
#define MBAR_ARRIVE(mbar) \
    asm volatile("mbarrier.arrive.shared.b64 _, [%0];" :: "r"(mbar) : "memory")
// hardware arrives on mbar when all prior cp.async of this thread complete
#define CP_MBAR_ARRIVE(mbar) \
    asm volatile("cp.async.mbarrier.arrive.noinc.shared.b64 [%0];" :: "r"(mbar) : "memory")
#define MBAR_WAIT(mbar, ph) \
    asm volatile("{\n\t.reg .pred p;\n\t" \
                 "WL%=:\n\t" \
                 "mbarrier.try_wait.parity.shared.b64 p, [%0], %1;\n\t" \
                 "@!p bra WL%=;\n\t}" :: "r"(mbar), "r"(ph) : "memory")

__device__ __forceinline__ uint32_t pk2h(float a, float b) {
    __half2 h = __floats2half2_rn(a, b);         // low = a, high = b
    return *(uint32_t*)&h;
}
__device__ __forceinline__ float silu_f(float v) {
    return __fdividef(v, 1.0f + __expf(-v));
}

// ============================================================================
// Prep: W[k][n] -> padded [n][SP] fp16 hi/lo images (layer 3 zero-padded)
// ============================================================================
__global__ __launch_bounds__(256)
void prep_weights(const float* __restrict__ W0, const float* __restrict__ W1,
                  const float* __restrict__ W2, const float* __restrict__ W3) {
    int e = blockIdx.x * 256 + threadIdx.x;        // over 4*128*128
    if (e >= 4 * 128 * 128) return;
    int l = e >> 14, r = e & 16383, n = r >> 7, k = r & 127;
    float v;
    if (l < 3) {
        const float* W = (l == 0) ? W0 : ((l == 1) ? W1 : W2);
        v = W[k * 128 + n];
    } else {
        v = (n < NC) ? W3[k * NC + n] : 0.0f;
    }
    __half* gw = (__half*)g_Wp4;
    size_t base = (size_t)l * (2 * 128 * SP);
    __half h = __float2half_rn(v);
    gw[base + n * SP + k] = h;
    gw[base + 128 * SP + n * SP + k] = __float2half_rn(v - __half2float(h));
}

// async-copy one layer image into a smem buffer (no commit; mbar-tracked)
__device__ __forceinline__ void cpasync_img(uint32_t dst, int layer, int tid) {
    const uint4* src = g_Wp4 + (size_t)layer * LAYER_U4;
    for (int i = tid; i < LAYER_U4; i += THREADS)
        CP_ASYNC16(dst + (uint32_t)i * 16, src + i);
}

// one hidden layer for BOTH row-sets: A(fp16 regs) x (Bhi+Blo) -> silu -> next A
__device__ __forceinline__ void hidden_layer(
    const uint32_t Ah[2][8][4], uint32_t Nh[2][8][4],
    uint32_t bufbase, const float* __restrict__ bias,
    uint32_t ofsB, int q)
{
#pragma unroll
    for (int p = 0; p < 8; p++) {              // n-tile pairs (cols 16p..16p+15)
        const float2 bA = __ldg((const float2*)(bias + 16 * p + 2 * q));
        const float2 bB = __ldg((const float2*)(bias + 16 * p + 8 + 2 * q));
        float c[2][8];
#pragma unroll
        for (int s = 0; s < 2; s++) {
            c[s][0] = bA.x; c[s][1] = bA.y; c[s][2] = bA.x; c[s][3] = bA.y;
            c[s][4] = bB.x; c[s][5] = bB.y; c[s][6] = bB.x; c[s][7] = bB.y;
        }
        const uint32_t pb = bufbase + (uint32_t)(p * 16 * SP) * 2 + ofsB;
#pragma unroll
        for (int kt = 0; kt < 8; kt++) {
            const uint32_t ba = pb + kt * 32;
            uint32_t h0, h1, h2, h3, l0, l1, l2, l3;
            LDSM4(h0, h1, h2, h3, ba);
            LDSM4(l0, l1, l2, l3, ba + HALF_BYTES);
            // 8 MMAs, 4 independent chains (s x n-half), dep distance 4
            MMA(c[0][0], c[0][1], c[0][2], c[0][3], Ah[0][kt][0], Ah[0][kt][1], Ah[0][kt][2], Ah[0][kt][3], h0, h1);
            MMA(c[0][4], c[0][5], c[0][6], c[0][7], Ah[0][kt][0], Ah[0][kt][1], Ah[0][kt][2], Ah[0][kt][3], h2, h3);
            MMA(c[1][0], c[1][1], c[1][2], c[1][3], Ah[1][kt][0], Ah[1][kt][1], Ah[1][kt][2], Ah[1][kt][3], h0, h1);
            MMA(c[1][4], c[1][5], c[1][6], c[1][7], Ah[1][kt][0], Ah[1][kt][1], Ah[1][kt][2], Ah[1][kt][3], h2, h3);
            MMA(c[0][0], c[0][1], c[0][2], c[0][3], Ah[0][kt][0], Ah[0][kt][1], Ah[0][kt][2], Ah[0][kt][3], l0, l1);
            MMA(c[0][4], c[0][5], c[0][6], c[0][7], Ah[0][kt][0], Ah[0][kt][1], Ah[0][kt][2], Ah[0][kt][3], l2, l3);
            MMA(c[1][0], c[1][1], c[1][2], c[1][3], Ah[1][kt][0], Ah[1][kt][1], Ah[1][kt][2], Ah[1][kt][3], l0, l1);
            MMA(c[1][4], c[1][5], c[1][6], c[1][7], Ah[1][kt][0], Ah[1][kt][1], Ah[1][kt][2], Ah[1][kt][3], l2, l3);
        }
        // C-frag == A-frag: silu + fp16 pack -> next layer k-tile p fragments
#pragma unroll
        for (int s = 0; s < 2; s++) {
            Nh[s][p][0] = pk2h(silu_f(c[s][0]), silu_f(c[s][1]));
            Nh[s][p][1] = pk2h(silu_f(c[s][2]), silu_f(c[s][3]));
            Nh[s][p][2] = pk2h(silu_f(c[s][4]), silu_f(c[s][5]));
            Nh[s][p][3] = pk2h(silu_f(c[s][6]), silu_f(c[s][7]));
        }
    }
}

// ============================================================================
// Main kernel
// ============================================================================
__global__ __launch_bounds__(THREADS)
void chebnet_mma_kernel(
    const float* __restrict__ x,
    const float* __restrict__ b0, const float* __restrict__ b1,
    const float* __restrict__ b2, const float* __restrict__ b3,
    float* __restrict__ out)
{
    extern __shared__ char sm[];
    const uint32_t smb = s2u(sm);
    const int tid  = threadIdx.x;
    const int lane = tid & 31;
    const int warp = tid >> 5;
    const int row0 = blockIdx.x * MB + warp * 32;   // this warp's 32 rows
    const int r    = lane >> 2;        // 0..7
    const int q    = lane & 3;

    const uint32_t ofsB = ((uint32_t)(((lane & 7) + ((lane & 16) >> 1)) * SP) * 2) + ((lane & 8) * 2);

    const uint32_t BUF0   = smb;
    const uint32_t BUF1   = smb + IMG_BYTES;
    const uint32_t BUF2   = smb + 2 * IMG_BYTES;
    const uint32_t ready0 = smb + MBAR_OFF;
    const uint32_t ready1 = smb + MBAR_OFF + 8;
    const uint32_t ready2 = smb + MBAR_OFF + 16;
    const uint32_t free0  = smb + MBAR_OFF + 24;

    // ---- mbarrier init (once), then prefetch L0/L1/L2 ----
    if (tid == 0) {
        MBAR_INIT(ready0, THREADS);
        MBAR_INIT(ready1, THREADS);
        MBAR_INIT(ready2, THREADS);
        MBAR_INIT(free0,  THREADS);
    }
    __syncthreads();                     // only block-wide barrier in the kernel

    cpasync_img(BUF0, 0, tid);  CP_MBAR_ARRIVE(ready0);
    cpasync_img(BUF1, 1, tid);  CP_MBAR_ARRIVE(ready1);
    cpasync_img(BUF2, 2, tid);  CP_MBAR_ARRIVE(ready2);

    // ---- load x into A fragments for both sets (clamped rows, last block) ----
    uint32_t Ah[2][8][4], Nh[2][8][4];
#pragma unroll
    for (int s = 0; s < 2; s++) {
        const int rA = row0 + s * 16 + r;
        const int rB = rA + 8;
        const int rAc = (rA < N_NODES) ? rA : (N_NODES - 1);
        const int rBc = (rB < N_NODES) ? rB : (N_NODES - 1);
        const float* xr0 = x + (size_t)rAc * DF;
        const float* xr8 = x + (size_t)rBc * DF;
#pragma unroll
        for (int kt = 0; kt < 8; kt++) {
            const int c = kt * 16 + 2 * q;
            float2 e0 = *(const float2*)(xr0 + c);
            float2 e1 = *(const float2*)(xr8 + c);
            float2 e2 = *(const float2*)(xr0 + c + 8);
            float2 e3 = *(const float2*)(xr8 + c + 8);
            Ah[s][kt][0] = pk2h(e0.x, e0.y);
            Ah[s][kt][1] = pk2h(e1.x, e1.y);
            Ah[s][kt][2] = pk2h(e2.x, e2.y);
            Ah[s][kt][3] = pk2h(e3.x, e3.y);
        }
    }

    // ---- layer 0 (BUF0) ----
    MBAR_WAIT(ready0, 0);
    hidden_layer(Ah, Nh, BUF0, b0, ofsB, q);
    MBAR_ARRIVE(free0);                  // done reading BUF0
#pragma unroll
    for (int i = 0; i < 8; i++)
#pragma unroll
        for (int j = 0; j < 4; j++) { Ah[0][i][j] = Nh[0][i][j]; Ah[1][i][j] = Nh[1][i][j]; }

    // ---- layer 1 (BUF1) ----
    MBAR_WAIT(ready1, 0);
    hidden_layer(Ah, Nh, BUF1, b1, ofsB, q);
#pragma unroll
    for (int i = 0; i < 8; i++)
#pragma unroll
        for (int j = 0; j < 4; j++) { Ah[0][i][j] = Nh[0][i][j]; Ah[1][i][j] = Nh[1][i][j]; }

    // ---- issue L3 -> BUF0 once every warp is done reading layer 0 ----
    MBAR_WAIT(free0, 0);
    cpasync_img(BUF0, 3, tid);  CP_MBAR_ARRIVE(ready0);   // ready0 -> phase 1

    // ---- layer 2 (BUF2) ----
    MBAR_WAIT(ready2, 0);
    hidden_layer(Ah, Nh, BUF2, b2, ofsB, q);
#pragma unroll
    for (int i = 0; i < 8; i++)
#pragma unroll
        for (int j = 0; j < 4; j++) { Ah[0][i][j] = Nh[0][i][j]; Ah[1][i][j] = Nh[1][i][j]; }

    // ---- output layer (BUF0, phase 1): N=40, both sets ----
    MBAR_WAIT(ready0, 1);
    {
        const uint32_t bufb = BUF0;
        float lgA[2][10], lgB[2][10];      // per set: rows r and r+8, 10 cols
#pragma unroll
        for (int p = 0; p < 2; p++) {      // n-tiles 0..3 (cols 0..31)
            const float2 bA = __ldg((const float2*)(b3 + 16 * p + 2 * q));
            const float2 bB = __ldg((const float2*)(b3 + 16 * p + 8 + 2 * q));
            float c[2][8];
#pragma unroll
            for (int s = 0; s < 2; s++) {
                c[s][0] = bA.x; c[s][1] = bA.y; c[s][2] = bA.x; c[s][3] = bA.y;
                c[s][4] = bB.x; c[s][5] = bB.y; c[s][6] = bB.x; c[s][7] = bB.y;
            }
            const uint32_t pb = bufb + (uint32_t)(p * 16 * SP) * 2 + ofsB;
#pragma unroll
            for (int kt = 0; kt < 8; kt++) {
                const uint32_t ba = pb + kt * 32;
                uint32_t h0, h1, h2, h3, l0, l1, l2, l3;
                LDSM4(h0, h1, h2, h3, ba);
                LDSM4(l0, l1, l2, l3, ba + HALF_BYTES);
                MMA(c[0][0], c[0][1], c[0][2], c[0][3], Ah[0][kt][0], Ah[0][kt][1], Ah[0][kt][2], Ah[0][kt][3], h0, h1);
                MMA(c[0][4], c[0][5], c[0][6], c[0][7], Ah[0][kt][0], Ah[0][kt][1], Ah[0][kt][2], Ah[0][kt][3], h2, h3);
                MMA(c[1][0], c[1][1], c[1][2], c[1][3], Ah[1][kt][0], Ah[1][kt][1], Ah[1][kt][2], Ah[1][kt][3], h0, h1);
                MMA(c[1][4], c[1][5], c[1][6], c[1][7], Ah[1][kt][0], Ah[1][kt][1], Ah[1][kt][2], Ah[1][kt][3], h2, h3);
                MMA(c[0][0], c[0][1], c[0][2], c[0][3], Ah[0][kt][0], Ah[0][kt][1], Ah[0][kt][2], Ah[0][kt][3], l0, l1);
                MMA(c[0][4], c[0][5], c[0][6], c[0][7], Ah[0][kt][0], Ah[0][kt][1], Ah[0][kt][2], Ah[0][kt][3], l2, l3);
                MMA(c[1][0], c[1][1], c[1][2], c[1][3], Ah[1][kt][0], Ah[1][kt][1], Ah[1][kt][2], Ah[1][kt][3], l0, l1);
                MMA(c[1][4], c[1][5], c[1][6], c[1][7], Ah[1][kt][0], Ah[1][kt][1], Ah[1][kt][2], Ah[1][kt][3], l2, l3);
            }
#pragma unroll
            for (int s = 0; s < 2; s++) {
                lgA[s][4 * p + 0] = c[s][0]; lgA[s][4 * p + 1] = c[s][1];
                lgB[s][4 * p + 0] = c[s][2]; lgB[s][4 * p + 1] = c[s][3];
                lgA[s][4 * p + 2] = c[s][4]; lgA[s][4 * p + 3] = c[s][5];
                lgB[s][4 * p + 2] = c[s][6]; lgB[s][4 * p + 3] = c[s][7];
            }
        }
        {   // n-tile 4 (cols 32..39)
            const float2 bA = __ldg((const float2*)(b3 + 32 + 2 * q));
            float c[2][4];
#pragma unroll
            for (int s = 0; s < 2; s++) {
                c[s][0] = bA.x; c[s][1] = bA.y; c[s][2] = bA.x; c[s][3] = bA.y;
            }
            const int r2 = lane & 15;
            const uint32_t cb = bufb + (uint32_t)((32 + (r2 & 7)) * SP) * 2 + (r2 & 8) * 2;
#pragma unroll
            for (int kt = 0; kt < 8; kt++) {
                const uint32_t ba = cb + kt * 32;
                uint32_t h0, h1, l0, l1;
                LDSM2(h0, h1, ba);
                LDSM2(l0, l1, ba + HALF_BYTES);
                MMA(c[0][0], c[0][1], c[0][2], c[0][3], Ah[0][kt][0], Ah[0][kt][1], Ah[0][kt][2], Ah[0][kt][3], h0, h1);
                MMA(c[1][0], c[1][1], c[1][2], c[1][3], Ah[1][kt][0], Ah[1][kt][1], Ah[1][kt][2], Ah[1][kt][3], h0, h1);
                MMA(c[0][0], c[0][1], c[0][2], c[0][3], Ah[0][kt][0], Ah[0][kt][1], Ah[0][kt][2], Ah[0][kt][3], l0, l1);
                MMA(c[1][0], c[1][1], c[1][2], c[1][3], Ah[1][kt][0], Ah[1][kt][1], Ah[1][kt][2], Ah[1][kt][3], l0, l1);
            }
#pragma unroll
            for (int s = 0; s < 2; s++) {
                lgA[s][8] = c[s][0]; lgA[s][9] = c[s][1];
                lgB[s][8] = c[s][2]; lgB[s][9] = c[s][3];
            }
        }

        // ---- log-softmax + store, per set ----
#pragma unroll
        for (int s = 0; s < 2; s++) {
            float mA = lgA[s][0], mB = lgB[s][0];
#pragma unroll
            for (int i = 1; i < 10; i++) { mA = fmaxf(mA, lgA[s][i]); mB = fmaxf(mB, lgB[s][i]); }
            mA = fmaxf(mA, __shfl_xor_sync(0xFFFFFFFF, mA, 1));
            mA = fmaxf(mA, __shfl_xor_sync(0xFFFFFFFF, mA, 2));
            mB = fmaxf(mB, __shfl_xor_sync(0xFFFFFFFF, mB, 1));
            mB = fmaxf(mB, __shfl_xor_sync(0xFFFFFFFF, mB, 2));
            float sA = 0.f, sB = 0.f;
#pragma unroll
            for (int i = 0; i < 10; i++) {
                sA += __expf(lgA[s][i] - mA);
                sB += __expf(lgB[s][i] - mB);
            }
            sA += __shfl_xor_sync(0xFFFFFFFF, sA, 1);
            sA += __shfl_xor_sync(0xFFFFFFFF, sA, 2);
            sB += __shfl_xor_sync(0xFFFFFFFF, sB, 1);
            sB += __shfl_xor_sync(0xFFFFFFFF, sB, 2);
            const float lseA = mA + __logf(sA);
            const float lseB = mB + __logf(sB);

            const int rA = row0 + s * 16 + r;
            const int rB = rA + 8;
            if (rA < N_NODES) {
                float* oA = out + (size_t)rA * NC + 2 * q;
#pragma unroll
                for (int nt = 0; nt < 5; nt++)
                    *(float2*)(oA + 8 * nt) =
                        make_float2(lgA[s][2 * nt] - lseA, lgA[s][2 * nt + 1] - lseA);
            }
            if (rB < N_NODES) {
                float* oB = out + (size_t)rB * NC + 2 * q;
#pragma unroll
                for (int nt = 0; nt < 5; nt++)
                    *(float2*)(oB + 8 * nt) =
                        make_float2(lgB[s][2 * nt] - lseB, lgB[s][2 * nt + 1] - lseB);
            }
        }
    }
}

// ============================================================================
// Inputs: x, edge_index(dead), W0,b0, W1,b1, W2,b2, W3,b3
// ============================================================================
extern "C" void kernel_launch(void* const* d_in, const int* in_sizes, int n_in,
                              void* d_out, int out_size)
{
    (void)in_sizes; (void)n_in; (void)out_size;
    const float* x  = (const float*)d_in[0];
    const float* W0 = (const float*)d_in[2];
    const float* b0 = (const float*)d_in[3];
    const float* W1 = (const float*)d_in[4];
    const float* b1 = (const float*)d_in[5];
    const float* W2 = (const float*)d_in[6];
    const float* b2 = (const float*)d_in[7];
    const float* W3 = (const float*)d_in[8];
    const float* b3 = (const float*)d_in[9];
    float* out = (float*)d_out;

    cudaFuncSetAttribute(chebnet_mma_kernel,
                         cudaFuncAttributeMaxDynamicSharedMemorySize, SMEM_TOTAL);

    prep_weights<<<(4 * 128 * 128) / 256, 256>>>(W0, W1, W2, W3);
    chebnet_mma_kernel<<<NBLOCKS, THREADS, SMEM_TOTAL>>>(x, b0, b1, b2, b3, out);
}

// round 16
// speedup vs baseline: 1.8843x; 1.0208x over previous
#include <cuda_runtime.h>
#include <cuda_fp16.h>
#include <cstdint>

// ============================================================================
// ChebConvNet fused MLP via mma.sync (HMMA fp16, baseline PTX).
//   h=silu(x@W0+b0); h=silu(h@W1+b1); h=silu(h@W2+b2); out=log_softmax(h@W3+b3)
// 12 warps x 32 rows/warp, A register-resident (C-frag == A-frag chaining),
// fp16 2-term weight split (Bhi+Blo), fp32 accumulate.
// Barrier-free layer pipeline: 3 smem weight buffers + mbarrier sync
// (cp.async.mbarrier.arrive), warps free-run across layers.
// NEW: silu via tanh.approx.f16x2 -- silu(x) = (x/2)(1+tanh(x/2)) computed
// packed fp16x2: 1 MUFU per TWO values (was 2 MUFU per value, 4x cut), result
// lands directly in next layer's packed A fragment. Ping-pong A/N fragment
// arrays (no copy-back).
// ============================================================================

#define N_NODES 200000
#define DF      128
#define NC      40
#define THREADS 384
#define MB      384                          // 12 warps x 32 rows
#define NBLOCKS ((N_NODES + MB - 1) / MB)    // 521

#define SP 136                               // padded row stride (fp16 elems)
#define IMG_BYTES  (2 * 128 * SP * 2)        // 69632: one layer image (hi+lo)
#define LAYER_U4   (IMG_BYTES / 16)          // 4352
#define HALF_BYTES (128 * SP * 2)            // 34816: lo offset inside image
#define MBAR_OFF   (3 * IMG_BYTES)           // 208896
#define SMEM_TOTAL (MBAR_OFF + 64)           // 208960 (3 bufs + 4 mbarriers)

// Prepped weights: per layer, [n:128][k:SP] fp16 hi then lo. L3 rows 40..127=0.
__device__ uint4 g_Wp4[4 * LAYER_U4];

__device__ __forceinline__ uint32_t s2u(const void* p) {
    uint32_t a;
    asm("{ .reg .u64 t; cvta.to.shared.u64 t, %1; cvt.u32.u64 %0, t; }" : "=r"(a) : "l"(p));
    return a;
}

#define LDSM4(r0, r1, r2, r3, a) \
    asm volatile("ldmatrix.sync.aligned.m8n8.x4.shared.b16 {%0,%1,%2,%3}, [%4];" \
                 : "=r"(r0), "=r"(r1), "=r"(r2), "=r"(r3) : "r"(a))
#define LDSM2(r0, r1, a) \
    asm volatile("ldmatrix.sync.aligned.m8n8.x2.shared.b16 {%0,%1}, [%2];" \
                 : "=r"(r0), "=r"(r1) : "r"(a))
#define MMA(c0, c1, c2, c3, a0, a1, a2, a3, b0, b1) \
    asm volatile("mma.sync.aligned.m16n8k16.row.col.f32.f16.f16.f32 " \
                 "{%0,%1,%2,%3}, {%4,%5,%6,%7}, {%8,%9}, {%0,%1,%2,%3};" \
                 : "+f"(c0), "+f"(c1), "+f"(c2), "+f"(c3) \
                 : "r"(a0), "r"(a1), "r"(a2), "r"(a3), "r"(b0), "r"(b1))

#define CP_ASYNC16(dst, src) \
    asm volatile("cp.async.cg.shared.global [%0], [%1], 16;" \
                 :: "r"(dst), "l"(src) : "memory")

// mbarrier (baseline PTX)
#define MBAR_INIT(mbar, cnt) \
    asm volatile("mbarrier.init.shared.b64 [%0], %1;" :: "r"(mbar), "r"(cnt) : "memory")
#define MBAR_ARRIVE(mbar) \
    asm volatile("mbarrier.arrive.shared.b64 _, [%0];" :: "r"(mbar) : "memory")
#define CP_MBAR_ARRIVE(mbar) \
    asm volatile("cp.async.mbarrier.arrive.noinc.shared.b64 [%0];" :: "r"(mbar) : "memory")
#define MBAR_WAIT(mbar, ph) \
    asm volatile("{\n\t.reg .pred p;\n\t" \
                 "WL%=:\n\t" \
                 "mbarrier.try_wait.parity.shared.b64 p, [%0], %1;\n\t" \
                 "@!p bra WL%=;\n\t}" :: "r"(mbar), "r"(ph) : "memory")

__device__ __forceinline__ uint32_t pk2h(float a, float b) {
    __half2 h = __floats2half2_rn(a, b);         // low = a, high = b
    return *(uint32_t*)&h;
}
// silu of a fp32 pair -> packed fp16x2, via tanh.approx.f16x2 (1 MUFU / 2 vals)
// silu(x) = (x/2) * (1 + tanh(x/2)) = hx*t + hx with hx = x/2
__device__ __forceinline__ uint32_t silu2h(float a, float b) {
    uint32_t hx = pk2h(0.5f * a, 0.5f * b), t, res;
    asm("tanh.approx.f16x2 %0, %1;" : "=r"(t) : "r"(hx));
    asm("fma.rn.f16x2 %0, %1, %2, %1;" : "=r"(res) : "r"(hx), "r"(t));
    return res;
}
__device__ __forceinline__ float silu_f(float v) {       // epilogue only
    return __fdividef(v, 1.0f + __expf(-v));
}

// ============================================================================
// Prep: W[k][n] -> padded [n][SP] fp16 hi/lo images (layer 3 zero-padded)
// ============================================================================
__global__ __launch_bounds__(256)
void prep_weights(const float* __restrict__ W0, const float* __restrict__ W1,
                  const float* __restrict__ W2, const float* __restrict__ W3) {
    int e = blockIdx.x * 256 + threadIdx.x;        // over 4*128*128
    if (e >= 4 * 128 * 128) return;
    int l = e >> 14, r = e & 16383, n = r >> 7, k = r & 127;
    float v;
    if (l < 3) {
        const float* W = (l == 0) ? W0 : ((l == 1) ? W1 : W2);
        v = W[k * 128 + n];
    } else {
        v = (n < NC) ? W3[k * NC + n] : 0.0f;
    }
    __half* gw = (__half*)g_Wp4;
    size_t base = (size_t)l * (2 * 128 * SP);
    __half h = __float2half_rn(v);
    gw[base + n * SP + k] = h;
    gw[base + 128 * SP + n * SP + k] = __float2half_rn(v - __half2float(h));
}

// async-copy one layer image into a smem buffer (no commit; mbar-tracked)
__device__ __forceinline__ void cpasync_img(uint32_t dst, int layer, int tid) {
    const uint4* src = g_Wp4 + (size_t)layer * LAYER_U4;
    for (int i = tid; i < LAYER_U4; i += THREADS)
        CP_ASYNC16(dst + (uint32_t)i * 16, src + i);
}

// one hidden layer for BOTH row-sets: A(fp16 regs) x (Bhi+Blo) -> silu -> next A
__device__ __forceinline__ void hidden_layer(
    const uint32_t Ah[2][8][4], uint32_t Nh[2][8][4],
    uint32_t bufbase, const float* __restrict__ bias,
    uint32_t ofsB, int q)
{
#pragma unroll
    for (int p = 0; p < 8; p++) {              // n-tile pairs (cols 16p..16p+15)
        const float2 bA = __ldg((const float2*)(bias + 16 * p + 2 * q));
        const float2 bB = __ldg((const float2*)(bias + 16 * p + 8 + 2 * q));
        float c[2][8];
#pragma unroll
        for (int s = 0; s < 2; s++) {
            c[s][0] = bA.x; c[s][1] = bA.y; c[s][2] = bA.x; c[s][3] = bA.y;
            c[s][4] = bB.x; c[s][5] = bB.y; c[s][6] = bB.x; c[s][7] = bB.y;
        }
        const uint32_t pb = bufbase + (uint32_t)(p * 16 * SP) * 2 + ofsB;
#pragma unroll
        for (int kt = 0; kt < 8; kt++) {
            const uint32_t ba = pb + kt * 32;
            uint32_t h0, h1, h2, h3, l0, l1, l2, l3;
            LDSM4(h0, h1, h2, h3, ba);
            LDSM4(l0, l1, l2, l3, ba + HALF_BYTES);
            // 8 MMAs, 4 independent chains (s x n-half), dep distance 4
            MMA(c[0][0], c[0][1], c[0][2], c[0][3], Ah[0][kt][0], Ah[0][kt][1], Ah[0][kt][2], Ah[0][kt][3], h0, h1);
            MMA(c[0][4], c[0][5], c[0][6], c[0][7], Ah[0][kt][0], Ah[0][kt][1], Ah[0][kt][2], Ah[0][kt][3], h2, h3);
            MMA(c[1][0], c[1][1], c[1][2], c[1][3], Ah[1][kt][0], Ah[1][kt][1], Ah[1][kt][2], Ah[1][kt][3], h0, h1);
            MMA(c[1][4], c[1][5], c[1][6], c[1][7], Ah[1][kt][0], Ah[1][kt][1], Ah[1][kt][2], Ah[1][kt][3], h2, h3);
            MMA(c[0][0], c[0][1], c[0][2], c[0][3], Ah[0][kt][0], Ah[0][kt][1], Ah[0][kt][2], Ah[0][kt][3], l0, l1);
            MMA(c[0][4], c[0][5], c[0][6], c[0][7], Ah[0][kt][0], Ah[0][kt][1], Ah[0][kt][2], Ah[0][kt][3], l2, l3);
            MMA(c[1][0], c[1][1], c[1][2], c[1][3], Ah[1][kt][0], Ah[1][kt][1], Ah[1][kt][2], Ah[1][kt][3], l0, l1);
            MMA(c[1][4], c[1][5], c[1][6], c[1][7], Ah[1][kt][0], Ah[1][kt][1], Ah[1][kt][2], Ah[1][kt][3], l2, l3);
        }
        // C-frag == A-frag: packed tanh-silu -> next layer k-tile p fragments
#pragma unroll
        for (int s = 0; s < 2; s++) {
            Nh[s][p][0] = silu2h(c[s][0], c[s][1]);
            Nh[s][p][1] = silu2h(c[s][2], c[s][3]);
            Nh[s][p][2] = silu2h(c[s][4], c[s][5]);
            Nh[s][p][3] = silu2h(c[s][6], c[s][7]);
        }
    }
}

// ============================================================================
// Main kernel
// ============================================================================
__global__ __launch_bounds__(THREADS)
void chebnet_mma_kernel(
    const float* __restrict__ x,
    const float* __restrict__ b0, const float* __restrict__ b1,
    const float* __restrict__ b2, const float* __restrict__ b3,
    float* __restrict__ out)
{
    extern __shared__ char sm[];
    const uint32_t smb = s2u(sm);
    const int tid  = threadIdx.x;
    const int lane = tid & 31;
    const int warp = tid >> 5;
    const int row0 = blockIdx.x * MB + warp * 32;   // this warp's 32 rows
    const int r    = lane >> 2;        // 0..7
    const int q    = lane & 3;

    const uint32_t ofsB = ((uint32_t)(((lane & 7) + ((lane & 16) >> 1)) * SP) * 2) + ((lane & 8) * 2);

    const uint32_t BUF0   = smb;
    const uint32_t BUF1   = smb + IMG_BYTES;
    const uint32_t BUF2   = smb + 2 * IMG_BYTES;
    const uint32_t ready0 = smb + MBAR_OFF;
    const uint32_t ready1 = smb + MBAR_OFF + 8;
    const uint32_t ready2 = smb + MBAR_OFF + 16;
    const uint32_t free0  = smb + MBAR_OFF + 24;

    // ---- mbarrier init (once), then prefetch L0/L1/L2 ----
    if (tid == 0) {
        MBAR_INIT(ready0, THREADS);
        MBAR_INIT(ready1, THREADS);
        MBAR_INIT(ready2, THREADS);
        MBAR_INIT(free0,  THREADS);
    }
    __syncthreads();                     // only block-wide barrier in the kernel

    cpasync_img(BUF0, 0, tid);  CP_MBAR_ARRIVE(ready0);
    cpasync_img(BUF1, 1, tid);  CP_MBAR_ARRIVE(ready1);
    cpasync_img(BUF2, 2, tid);  CP_MBAR_ARRIVE(ready2);

    // ---- load x into A fragments for both sets (clamped rows, last block) ----
    uint32_t Ah[2][8][4], Nh[2][8][4];
#pragma unroll
    for (int s = 0; s < 2; s++) {
        const int rA = row0 + s * 16 + r;
        const int rB = rA + 8;
        const int rAc = (rA < N_NODES) ? rA : (N_NODES - 1);
        const int rBc = (rB < N_NODES) ? rB : (N_NODES - 1);
        const float* xr0 = x + (size_t)rAc * DF;
        const float* xr8 = x + (size_t)rBc * DF;
#pragma unroll
        for (int kt = 0; kt < 8; kt++) {
            const int c = kt * 16 + 2 * q;
            float2 e0 = *(const float2*)(xr0 + c);
            float2 e1 = *(const float2*)(xr8 + c);
            float2 e2 = *(const float2*)(xr0 + c + 8);
            float2 e3 = *(const float2*)(xr8 + c + 8);
            Ah[s][kt][0] = pk2h(e0.x, e0.y);
            Ah[s][kt][1] = pk2h(e1.x, e1.y);
            Ah[s][kt][2] = pk2h(e2.x, e2.y);
            Ah[s][kt][3] = pk2h(e3.x, e3.y);
        }
    }

    // ---- layer 0 (BUF0): Ah -> Nh ----
    MBAR_WAIT(ready0, 0);
    hidden_layer(Ah, Nh, BUF0, b0, ofsB, q);
    MBAR_ARRIVE(free0);                  // done reading BUF0

    // ---- layer 1 (BUF1): Nh -> Ah ----
    MBAR_WAIT(ready1, 0);
    hidden_layer(Nh, Ah, BUF1, b1, ofsB, q);

    // ---- issue L3 -> BUF0 once every warp is done reading layer 0 ----
    MBAR_WAIT(free0, 0);
    cpasync_img(BUF0, 3, tid);  CP_MBAR_ARRIVE(ready0);   // ready0 -> phase 1

    // ---- layer 2 (BUF2): Ah -> Nh ----
    MBAR_WAIT(ready2, 0);
    hidden_layer(Ah, Nh, BUF2, b2, ofsB, q);

    // ---- output layer (BUF0, phase 1): N=40, activations in Nh ----
    MBAR_WAIT(ready0, 1);
    {
        const uint32_t bufb = BUF0;
        float lgA[2][10], lgB[2][10];      // per set: rows r and r+8, 10 cols
#pragma unroll
        for (int p = 0; p < 2; p++) {      // n-tiles 0..3 (cols 0..31)
            const float2 bA = __ldg((const float2*)(b3 + 16 * p + 2 * q));
            const float2 bB = __ldg((const float2*)(b3 + 16 * p + 8 + 2 * q));
            float c[2][8];
#pragma unroll
            for (int s = 0; s < 2; s++) {
                c[s][0] = bA.x; c[s][1] = bA.y; c[s][2] = bA.x; c[s][3] = bA.y;
                c[s][4] = bB.x; c[s][5] = bB.y; c[s][6] = bB.x; c[s][7] = bB.y;
            }
            const uint32_t pb = bufb + (uint32_t)(p * 16 * SP) * 2 + ofsB;
#pragma unroll
            for (int kt = 0; kt < 8; kt++) {
                const uint32_t ba = pb + kt * 32;
                uint32_t h0, h1, h2, h3, l0, l1, l2, l3;
                LDSM4(h0, h1, h2, h3, ba);
                LDSM4(l0, l1, l2, l3, ba + HALF_BYTES);
                MMA(c[0][0], c[0][1], c[0][2], c[0][3], Nh[0][kt][0], Nh[0][kt][1], Nh[0][kt][2], Nh[0][kt][3], h0, h1);
                MMA(c[0][4], c[0][5], c[0][6], c[0][7], Nh[0][kt][0], Nh[0][kt][1], Nh[0][kt][2], Nh[0][kt][3], h2, h3);
                MMA(c[1][0], c[1][1], c[1][2], c[1][3], Nh[1][kt][0], Nh[1][kt][1], Nh[1][kt][2], Nh[1][kt][3], h0, h1);
                MMA(c[1][4], c[1][5], c[1][6], c[1][7], Nh[1][kt][0], Nh[1][kt][1], Nh[1][kt][2], Nh[1][kt][3], h2, h3);
                MMA(c[0][0], c[0][1], c[0][2], c[0][3], Nh[0][kt][0], Nh[0][kt][1], Nh[0][kt][2], Nh[0][kt][3], l0, l1);
                MMA(c[0][4], c[0][5], c[0][6], c[0][7], Nh[0][kt][0], Nh[0][kt][1], Nh[0][kt][2], Nh[0][kt][3], l2, l3);
                MMA(c[1][0], c[1][1], c[1][2], c[1][3], Nh[1][kt][0], Nh[1][kt][1], Nh[1][kt][2], Nh[1][kt][3], l0, l1);
                MMA(c[1][4], c[1][5], c[1][6], c[1][7], Nh[1][kt][0], Nh[1][kt][1], Nh[1][kt][2], Nh[1][kt][3], l2, l3);
            }
#pragma unroll
            for (int s = 0; s < 2; s++) {
                lgA[s][4 * p + 0] = c[s][0]; lgA[s][4 * p + 1] = c[s][1];
                lgB[s][4 * p + 0] = c[s][2]; lgB[s][4 * p + 1] = c[s][3];
                lgA[s][4 * p + 2] = c[s][4]; lgA[s][4 * p + 3] = c[s][5];
                lgB[s][4 * p + 2] = c[s][6]; lgB[s][4 * p + 3] = c[s][7];
            }
        }
        {   // n-tile 4 (cols 32..39)
            const float2 bA = __ldg((const float2*)(b3 + 32 + 2 * q));
            float c[2][4];
#pragma unroll
            for (int s = 0; s < 2; s++) {
                c[s][0] = bA.x; c[s][1] = bA.y; c[s][2] = bA.x; c[s][3] = bA.y;
            }
            const int r2 = lane & 15;
            const uint32_t cb = bufb + (uint32_t)((32 + (r2 & 7)) * SP) * 2 + (r2 & 8) * 2;
#pragma unroll
            for (int kt = 0; kt < 8; kt++) {
                const uint32_t ba = cb + kt * 32;
                uint32_t h0, h1, l0, l1;
                LDSM2(h0, h1, ba);
                LDSM2(l0, l1, ba + HALF_BYTES);
                MMA(c[0][0], c[0][1], c[0][2], c[0][3], Nh[0][kt][0], Nh[0][kt][1], Nh[0][kt][2], Nh[0][kt][3], h0, h1);
                MMA(c[1][0], c[1][1], c[1][2], c[1][3], Nh[1][kt][0], Nh[1][kt][1], Nh[1][kt][2], Nh[1][kt][3], h0, h1);
                MMA(c[0][0], c[0][1], c[0][2], c[0][3], Nh[0][kt][0], Nh[0][kt][1], Nh[0][kt][2], Nh[0][kt][3], l0, l1);
                MMA(c[1][0], c[1][1], c[1][2], c[1][3], Nh[1][kt][0], Nh[1][kt][1], Nh[1][kt][2], Nh[1][kt][3], l0, l1);
            }
#pragma unroll
            for (int s = 0; s < 2; s++) {
                lgA[s][8] = c[s][0]; lgA[s][9] = c[s][1];
                lgB[s][8] = c[s][2]; lgB[s][9] = c[s][3];
            }
        }

        // ---- log-softmax + store, per set ----
#pragma unroll
        for (int s = 0; s < 2; s++) {
            float mA = lgA[s][0], mB = lgB[s][0];
#pragma unroll
            for (int i = 1; i < 10; i++) { mA = fmaxf(mA, lgA[s][i]); mB = fmaxf(mB, lgB[s][i]); }
            mA = fmaxf(mA, __shfl_xor_sync(0xFFFFFFFF, mA, 1));
            mA = fmaxf(mA, __shfl_xor_sync(0xFFFFFFFF, mA, 2));
            mB = fmaxf(mB, __shfl_xor_sync(0xFFFFFFFF, mB, 1));
            mB = fmaxf(mB, __shfl_xor_sync(0xFFFFFFFF, mB, 2));
            float sA = 0.f, sB = 0.f;
#pragma unroll
            for (int i = 0; i < 10; i++) {
                sA += __expf(lgA[s][i] - mA);
                sB += __expf(lgB[s][i] - mB);
            }
            sA += __shfl_xor_sync(0xFFFFFFFF, sA, 1);
            sA += __shfl_xor_sync(0xFFFFFFFF, sA, 2);
            sB += __shfl_xor_sync(0xFFFFFFFF, sB, 1);
            sB += __shfl_xor_sync(0xFFFFFFFF, sB, 2);
            const float lseA = mA + __logf(sA);
            const float lseB = mB + __logf(sB);

            const int rA = row0 + s * 16 + r;
            const int rB = rA + 8;
            if (rA < N_NODES) {
                float* oA = out + (size_t)rA * NC + 2 * q;
#pragma unroll
                for (int nt = 0; nt < 5; nt++)
                    *(float2*)(oA + 8 * nt) =
                        make_float2(lgA[s][2 * nt] - lseA, lgA[s][2 * nt + 1] - lseA);
            }
            if (rB < N_NODES) {
                float* oB = out + (size_t)rB * NC + 2 * q;
#pragma unroll
                for (int nt = 0; nt < 5; nt++)
                    *(float2*)(oB + 8 * nt) =
                        make_float2(lgB[s][2 * nt] - lseB, lgB[s][2 * nt + 1] - lseB);
            }
        }
    }
}

// ============================================================================
// Inputs: x, edge_index(dead), W0,b0, W1,b1, W2,b2, W3,b3
// ============================================================================
extern "C" void kernel_launch(void* const* d_in, const int* in_sizes, int n_in,
                              void* d_out, int out_size)
{
    (void)in_sizes; (void)n_in; (void)out_size;
    const float* x  = (const float*)d_in[0];
    const float* W0 = (const float*)d_in[2];
    const float* b0 = (const float*)d_in[3];
    const float* W1 = (const float*)d_in[4];
    const float* b1 = (const float*)d_in[5];
    const float* W2 = (const float*)d_in[6];
    const float* b2 = (const float*)d_in[7];
    const float* W3 = (const float*)d_in[8];
    const float* b3 = (const float*)d_in[9];
    float* out = (float*)d_out;

    cudaFuncSetAttribute(chebnet_mma_kernel,
                         cudaFuncAttributeMaxDynamicSharedMemorySize, SMEM_TOTAL);

    prep_weights<<<(4 * 128 * 128) / 256, 256>>>(W0, W1, W2, W3);
    chebnet_mma_kernel<<<NBLOCKS, THREADS, SMEM_TOTAL>>>(x, b0, b1, b2, b3, out);
}

// round 17
// speedup vs baseline: 3.0760x; 1.6324x over previous
#include <cuda_runtime.h>
#include <cuda_fp16.h>
#include <cstdint>

// ============================================================================
// ChebConvNet fused MLP via mma.sync (HMMA fp16, baseline PTX).
//   h=silu(x@W0+b0); h=silu(h@W1+b1); h=silu(h@W2+b2); out=log_softmax(h@W3+b3)
// 12 warps x 32 rows/warp, A register-resident (C-frag == A-frag chaining).
// Precision: A fp16 AND W fp16 (single, no split) -- error budget analysis:
// A-quant (2^-12) already dominates; W-quant adds the same magnitude ->
// expected rel_err ~5-8e-5 vs 1e-3 threshold. In exchange MMA count and
// B ldmatrix traffic HALVE, and one layer image is 34.8KB so ALL FOUR layer
// images fit in smem (139KB): one cp.async batch + ONE mbar wait at start,
// then zero synchronization for the whole kernel -- warps free-run through
// all 4 layers. silu via tanh.approx.f16x2 (1 MUFU / 2 values).
// ============================================================================

#define N_NODES 200000
#define DF      128
#define NC      40
#define THREADS 384
#define MB      384                          // 12 warps x 32 rows
#define NBLOCKS ((N_NODES + MB - 1) / MB)    // 521

#define SP 136                               // padded row stride (fp16 elems)
#define IMG_BYTES  (128 * SP * 2)            // 34816: one layer image (fp16)
#define IMG_U4     (IMG_BYTES / 16)          // 2176
#define TOTAL_U4   (4 * IMG_U4)              // 8704
#define MBAR_OFF   (4 * IMG_BYTES)           // 139264
#define SMEM_TOTAL (MBAR_OFF + 16)           // 139280

// Prepped weights: per layer, [n:128][k:SP] fp16. L3 rows 40..127 = 0.
__device__ uint4 g_W4[TOTAL_U4];

__device__ __forceinline__ uint32_t s2u(const void* p) {
    uint32_t a;
    asm("{ .reg .u64 t; cvta.to.shared.u64 t, %1; cvt.u32.u64 %0, t; }" : "=r"(a) : "l"(p));
    return a;
}

#define LDSM4(r0, r1, r2, r3, a) \
    asm volatile("ldmatrix.sync.aligned.m8n8.x4.shared.b16 {%0,%1,%2,%3}, [%4];" \
                 : "=r"(r0), "=r"(r1), "=r"(r2), "=r"(r3) : "r"(a))
#define LDSM2(r0, r1, a) \
    asm volatile("ldmatrix.sync.aligned.m8n8.x2.shared.b16 {%0,%1}, [%2];" \
                 : "=r"(r0), "=r"(r1) : "r"(a))
#define MMA(c0, c1, c2, c3, a0, a1, a2, a3, b0, b1) \
    asm volatile("mma.sync.aligned.m16n8k16.row.col.f32.f16.f16.f32 " \
                 "{%0,%1,%2,%3}, {%4,%5,%6,%7}, {%8,%9}, {%0,%1,%2,%3};" \
                 : "+f"(c0), "+f"(c1), "+f"(c2), "+f"(c3) \
                 : "r"(a0), "r"(a1), "r"(a2), "r"(a3), "r"(b0), "r"(b1))

#define CP_ASYNC16(dst, src) \
    asm volatile("cp.async.cg.shared.global [%0], [%1], 16;" \
                 :: "r"(dst), "l"(src) : "memory")

// mbarrier (baseline PTX)
#define MBAR_INIT(mbar, cnt) \
    asm volatile("mbarrier.init.shared.b64 [%0], %1;" :: "r"(mbar), "r"(cnt) : "memory")
#define CP_MBAR_ARRIVE(mbar) \
    asm volatile("cp.async.mbarrier.arrive.noinc.shared.b64 [%0];" :: "r"(mbar) : "memory")
#define MBAR_WAIT(mbar, ph) \
    asm volatile("{\n\t.reg .pred p;\n\t" \
                 "WL%=:\n\t" \
                 "mbarrier.try_wait.parity.shared.b64 p, [%0], %1;\n\t" \
                 "@!p bra WL%=;\n\t}" :: "r"(mbar), "r"(ph) : "memory")

__device__ __forceinline__ uint32_t pk2h(float a, float b) {
    __half2 h = __floats2half2_rn(a, b);         // low = a, high = b
    return *(uint32_t*)&h;
}
// silu of a fp32 pair -> packed fp16x2 via tanh.approx.f16x2 (1 MUFU / 2 vals)
__device__ __forceinline__ uint32_t silu2h(float a, float b) {
    uint32_t hx = pk2h(0.5f * a, 0.5f * b), t, res;
    asm("tanh.approx.f16x2 %0, %1;" : "=r"(t) : "r"(hx));
    asm("fma.rn.f16x2 %0, %1, %2, %1;" : "=r"(res) : "r"(hx), "r"(t));
    return res;
}

// ============================================================================
// Prep: W[k][n] -> padded [n][SP] fp16 images (layer 3 zero-padded rows>=40)
// ============================================================================
__global__ __launch_bounds__(256)
void prep_weights(const float* __restrict__ W0, const float* __restrict__ W1,
                  const float* __restrict__ W2, const float* __restrict__ W3) {
    int e = blockIdx.x * 256 + threadIdx.x;        // over 4*128*128
    if (e >= 4 * 128 * 128) return;
    int l = e >> 14, r = e & 16383, n = r >> 7, k = r & 127;
    float v;
    if (l < 3) {
        const float* W = (l == 0) ? W0 : ((l == 1) ? W1 : W2);
        v = W[k * 128 + n];
    } else {
        v = (n < NC) ? W3[k * NC + n] : 0.0f;
    }
    __half* gw = (__half*)g_W4;
    gw[(size_t)l * (128 * SP) + n * SP + k] = __float2half_rn(v);
}

// one hidden layer for BOTH row-sets: A(fp16 regs) x B(fp16 smem) -> silu -> A
__device__ __forceinline__ void hidden_layer(
    const uint32_t Ah[2][8][4], uint32_t Nh[2][8][4],
    uint32_t bufbase, const float* __restrict__ bias,
    uint32_t ofsB, int q)
{
#pragma unroll
    for (int p = 0; p < 8; p++) {              // n-tile pairs (cols 16p..16p+15)
        const float2 bA = __ldg((const float2*)(bias + 16 * p + 2 * q));
        const float2 bB = __ldg((const float2*)(bias + 16 * p + 8 + 2 * q));
        float c[2][8];
#pragma unroll
        for (int s = 0; s < 2; s++) {
            c[s][0] = bA.x; c[s][1] = bA.y; c[s][2] = bA.x; c[s][3] = bA.y;
            c[s][4] = bB.x; c[s][5] = bB.y; c[s][6] = bB.x; c[s][7] = bB.y;
        }
        const uint32_t pb = bufbase + (uint32_t)(p * 16 * SP) * 2 + ofsB;
#pragma unroll
        for (int kt = 0; kt < 8; kt++) {
            const uint32_t ba = pb + kt * 32;
            uint32_t h0, h1, h2, h3;
            LDSM4(h0, h1, h2, h3, ba);
            // 4 MMAs, 4 independent chains (s x n-half), dep distance 4
            MMA(c[0][0], c[0][1], c[0][2], c[0][3], Ah[0][kt][0], Ah[0][kt][1], Ah[0][kt][2], Ah[0][kt][3], h0, h1);
            MMA(c[0][4], c[0][5], c[0][6], c[0][7], Ah[0][kt][0], Ah[0][kt][1], Ah[0][kt][2], Ah[0][kt][3], h2, h3);
            MMA(c[1][0], c[1][1], c[1][2], c[1][3], Ah[1][kt][0], Ah[1][kt][1], Ah[1][kt][2], Ah[1][kt][3], h0, h1);
            MMA(c[1][4], c[1][5], c[1][6], c[1][7], Ah[1][kt][0], Ah[1][kt][1], Ah[1][kt][2], Ah[1][kt][3], h2, h3);
        }
        // C-frag == A-frag: packed tanh-silu -> next layer k-tile p fragments
#pragma unroll
        for (int s = 0; s < 2; s++) {
            Nh[s][p][0] = silu2h(c[s][0], c[s][1]);
            Nh[s][p][1] = silu2h(c[s][2], c[s][3]);
            Nh[s][p][2] = silu2h(c[s][4], c[s][5]);
            Nh[s][p][3] = silu2h(c[s][6], c[s][7]);
        }
    }
}

// ============================================================================
// Main kernel
// ============================================================================
__global__ __launch_bounds__(THREADS)
void chebnet_mma_kernel(
    const float* __restrict__ x,
    const float* __restrict__ b0, const float* __restrict__ b1,
    const float* __restrict__ b2, const float* __restrict__ b3,
    float* __restrict__ out)
{
    extern __shared__ char sm[];
    const uint32_t smb = s2u(sm);
    const int tid  = threadIdx.x;
    const int lane = tid & 31;
    const int warp = tid >> 5;
    const int row0 = blockIdx.x * MB + warp * 32;   // this warp's 32 rows
    const int r    = lane >> 2;        // 0..7
    const int q    = lane & 3;

    const uint32_t ofsB = ((uint32_t)(((lane & 7) + ((lane & 16) >> 1)) * SP) * 2) + ((lane & 8) * 2);
    const uint32_t ready = smb + MBAR_OFF;

    // ---- mbar init, then one cp.async batch for ALL FOUR layer images ----
    if (tid == 0) MBAR_INIT(ready, THREADS);
    __syncthreads();                     // only block-wide barrier in the kernel

    for (int i = tid; i < TOTAL_U4; i += THREADS)
        CP_ASYNC16(smb + (uint32_t)i * 16, g_W4 + i);
    CP_MBAR_ARRIVE(ready);

    // ---- load x into A fragments for both sets (clamped rows, last block) ----
    uint32_t Ah[2][8][4], Nh[2][8][4];
#pragma unroll
    for (int s = 0; s < 2; s++) {
        const int rA = row0 + s * 16 + r;
        const int rB = rA + 8;
        const int rAc = (rA < N_NODES) ? rA : (N_NODES - 1);
        const int rBc = (rB < N_NODES) ? rB : (N_NODES - 1);
        const float* xr0 = x + (size_t)rAc * DF;
        const float* xr8 = x + (size_t)rBc * DF;
#pragma unroll
        for (int kt = 0; kt < 8; kt++) {
            const int c = kt * 16 + 2 * q;
            float2 e0 = *(const float2*)(xr0 + c);
            float2 e1 = *(const float2*)(xr8 + c);
            float2 e2 = *(const float2*)(xr0 + c + 8);
            float2 e3 = *(const float2*)(xr8 + c + 8);
            Ah[s][kt][0] = pk2h(e0.x, e0.y);
            Ah[s][kt][1] = pk2h(e1.x, e1.y);
            Ah[s][kt][2] = pk2h(e2.x, e2.y);
            Ah[s][kt][3] = pk2h(e3.x, e3.y);
        }
    }

    // ---- single wait; then all layers free-run with NO synchronization ----
    MBAR_WAIT(ready, 0);
    hidden_layer(Ah, Nh, smb,                 b0, ofsB, q);   // layer 0
    hidden_layer(Nh, Ah, smb + IMG_BYTES,     b1, ofsB, q);   // layer 1
    hidden_layer(Ah, Nh, smb + 2 * IMG_BYTES, b2, ofsB, q);   // layer 2

    // ---- output layer (image 3): N=40, activations in Nh ----
    {
        const uint32_t bufb = smb + 3 * IMG_BYTES;
        float lgA[2][10], lgB[2][10];      // per set: rows r and r+8, 10 cols
#pragma unroll
        for (int p = 0; p < 2; p++) {      // n-tiles 0..3 (cols 0..31)
            const float2 bA = __ldg((const float2*)(b3 + 16 * p + 2 * q));
            const float2 bB = __ldg((const float2*)(b3 + 16 * p + 8 + 2 * q));
            float c[2][8];
#pragma unroll
            for (int s = 0; s < 2; s++) {
                c[s][0] = bA.x; c[s][1] = bA.y; c[s][2] = bA.x; c[s][3] = bA.y;
                c[s][4] = bB.x; c[s][5] = bB.y; c[s][6] = bB.x; c[s][7] = bB.y;
            }
            const uint32_t pb = bufb + (uint32_t)(p * 16 * SP) * 2 + ofsB;
#pragma unroll
            for (int kt = 0; kt < 8; kt++) {
                const uint32_t ba = pb + kt * 32;
                uint32_t h0, h1, h2, h3;
                LDSM4(h0, h1, h2, h3, ba);
                MMA(c[0][0], c[0][1], c[0][2], c[0][3], Nh[0][kt][0], Nh[0][kt][1], Nh[0][kt][2], Nh[0][kt][3], h0, h1);
                MMA(c[0][4], c[0][5], c[0][6], c[0][7], Nh[0][kt][0], Nh[0][kt][1], Nh[0][kt][2], Nh[0][kt][3], h2, h3);
                MMA(c[1][0], c[1][1], c[1][2], c[1][3], Nh[1][kt][0], Nh[1][kt][1], Nh[1][kt][2], Nh[1][kt][3], h0, h1);
                MMA(c[1][4], c[1][5], c[1][6], c[1][7], Nh[1][kt][0], Nh[1][kt][1], Nh[1][kt][2], Nh[1][kt][3], h2, h3);
            }
#pragma unroll
            for (int s = 0; s < 2; s++) {
                lgA[s][4 * p + 0] = c[s][0]; lgA[s][4 * p + 1] = c[s][1];
                lgB[s][4 * p + 0] = c[s][2]; lgB[s][4 * p + 1] = c[s][3];
                lgA[s][4 * p + 2] = c[s][4]; lgA[s][4 * p + 3] = c[s][5];
                lgB[s][4 * p + 2] = c[s][6]; lgB[s][4 * p + 3] = c[s][7];
            }
        }
        {   // n-tile 4 (cols 32..39)
            const float2 bA = __ldg((const float2*)(b3 + 32 + 2 * q));
            float c[2][4];
#pragma unroll
            for (int s = 0; s < 2; s++) {
                c[s][0] = bA.x; c[s][1] = bA.y; c[s][2] = bA.x; c[s][3] = bA.y;
            }
            const int r2 = lane & 15;
            const uint32_t cb = bufb + (uint32_t)((32 + (r2 & 7)) * SP) * 2 + (r2 & 8) * 2;
#pragma unroll
            for (int kt = 0; kt < 8; kt++) {
                const uint32_t ba = cb + kt * 32;
                uint32_t h0, h1;
                LDSM2(h0, h1, ba);
                MMA(c[0][0], c[0][1], c[0][2], c[0][3], Nh[0][kt][0], Nh[0][kt][1], Nh[0][kt][2], Nh[0][kt][3], h0, h1);
                MMA(c[1][0], c[1][1], c[1][2], c[1][3], Nh[1][kt][0], Nh[1][kt][1], Nh[1][kt][2], Nh[1][kt][3], h0, h1);
            }
#pragma unroll
            for (int s = 0; s < 2; s++) {
                lgA[s][8] = c[s][0]; lgA[s][9] = c[s][1];
                lgB[s][8] = c[s][2]; lgB[s][9] = c[s][3];
            }
        }

        // ---- log-softmax + store, per set ----
#pragma unroll
        for (int s = 0; s < 2; s++) {
            float mA = lgA[s][0], mB = lgB[s][0];
#pragma unroll
            for (int i = 1; i < 10; i++) { mA = fmaxf(mA, lgA[s][i]); mB = fmaxf(mB, lgB[s][i]); }
            mA = fmaxf(mA, __shfl_xor_sync(0xFFFFFFFF, mA, 1));
            mA = fmaxf(mA, __shfl_xor_sync(0xFFFFFFFF, mA, 2));
            mB = fmaxf(mB, __shfl_xor_sync(0xFFFFFFFF, mB, 1));
            mB = fmaxf(mB, __shfl_xor_sync(0xFFFFFFFF, mB, 2));
            float sA = 0.f, sB = 0.f;
#pragma unroll
            for (int i = 0; i < 10; i++) {
                sA += __expf(lgA[s][i] - mA);
                sB += __expf(lgB[s][i] - mB);
            }
            sA += __shfl_xor_sync(0xFFFFFFFF, sA, 1);
            sA += __shfl_xor_sync(0xFFFFFFFF, sA, 2);
            sB += __shfl_xor_sync(0xFFFFFFFF, sB, 1);
            sB += __shfl_xor_sync(0xFFFFFFFF, sB, 2);
            const float lseA = mA + __logf(sA);
            const float lseB = mB + __logf(sB);

            const int rA = row0 + s * 16 + r;
            const int rB = rA + 8;
            if (rA < N_NODES) {
                float* oA = out + (size_t)rA * NC + 2 * q;
#pragma unroll
                for (int nt = 0; nt < 5; nt++)
                    *(float2*)(oA + 8 * nt) =
                        make_float2(lgA[s][2 * nt] - lseA, lgA[s][2 * nt + 1] - lseA);
            }
            if (rB < N_NODES) {
                float* oB = out + (size_t)rB * NC + 2 * q;
#pragma unroll
                for (int nt = 0; nt < 5; nt++)
                    *(float2*)(oB + 8 * nt) =
                        make_float2(lgB[s][2 * nt] - lseB, lgB[s][2 * nt + 1] - lseB);
            }
        }
    }
}

// ============================================================================
// Inputs: x, edge_index(dead), W0,b0, W1,b1, W2,b2, W3,b3
// ============================================================================
extern "C" void kernel_launch(void* const* d_in, const int* in_sizes, int n_in,
                              void* d_out, int out_size)
{
    (void)in_sizes; (void)n_in; (void)out_size;
    const float* x  = (const float*)d_in[0];
    const float* W0 = (const float*)d_in[2];
    const float* b0 = (const float*)d_in[3];
    const float* W1 = (const float*)d_in[4];
    const float* b1 = (const float*)d_in[5];
    const float* W2 = (const float*)d_in[6];
    const float* b2 = (const float*)d_in[7];
    const float* W3 = (const float*)d_in[8];
    const float* b3 = (const float*)d_in[9];
    float* out = (float*)d_out;

    cudaFuncSetAttribute(chebnet_mma_kernel,
                         cudaFuncAttributeMaxDynamicSharedMemorySize, SMEM_TOTAL);

    prep_weights<<<(4 * 128 * 128) / 256, 256>>>(W0, W1, W2, W3);
    chebnet_mma_kernel<<<NBLOCKS, THREADS, SMEM_TOTAL>>>(x, b0, b1, b2, b3, out);
}